// round 4
// baseline (speedup 1.0000x reference)
#include <cuda_runtime.h>

#define NODES 50000
#define NE    800000
#define HID   128
#define NPART 32
#define BN_EPS 1e-5f
#define SBLK  512
#define NSB   ((NODES + SBLK - 1) / SBLK)   // 98

typedef unsigned long long ull;

// ---------------- scratch (device globals; no runtime alloc) ----------------
__device__ float g_deg[NODES];
__device__ int   g_cnt[NODES];
__device__ int   g_off[NODES + 1];
__device__ int   g_cur[NODES];
__device__ float g_dinv[NODES];
__device__ int   g_bsum[NSB];
__device__ int   g_boff[NSB];
__device__ int2  g_csr[NE];                 // {src, float_as_int(norm)}
__device__ float g_hw[NODES * HID];
__device__ float g_agg[NODES * HID];
__device__ float g_stats[3 * 2 * HID];      // per layer: [0:128) sum, [128:256) sumsq
__device__ float g_base[HID];
__device__ float g_we[HID];

// ---------------- f32x2 helpers ----------------
__device__ __forceinline__ ull pk2(float lo, float hi) {
    ull r;
    asm("mov.b64 %0, {%1, %2};" : "=l"(r) : "f"(lo), "f"(hi));
    return r;
}
__device__ __forceinline__ void fma2(ull& d, ull a, ull b) {
    asm("fma.rn.f32x2 %0, %1, %2, %0;" : "+l"(d) : "l"(a), "l"(b));
}
__device__ __forceinline__ float2 upk2(ull v) {
    float2 f;
    asm("mov.b64 {%0, %1}, %2;" : "=f"(f.x), "=f"(f.y) : "l"(v));
    return f;
}

// ---------------- init ----------------
__global__ void zero_init_kernel(float* out) {
    int i = blockIdx.x * blockDim.x + threadIdx.x;
    if (i < NODES) { g_deg[i] = 0.f; g_cnt[i] = 0; g_cur[i] = 0; }
    if (i < NPART) out[i] = 0.f;
    if (i < 3 * 2 * HID) g_stats[i] = 0.f;
}

// ---------------- degree + count ----------------
__global__ void deg_count_kernel(const int* __restrict__ ei,
                                 const float* __restrict__ ew) {
    int e = blockIdx.x * blockDim.x + threadIdx.x;
    if (e >= NE) return;
    int dst = ei[NE + e];
    atomicAdd(&g_deg[dst], ew[e]);
    atomicAdd(&g_cnt[dst], 1);
}

// ---------------- scan stage 1: per-block sums (+ dinv fused) ----------------
__global__ __launch_bounds__(SBLK) void block_sum_kernel() {
    __shared__ int ws[SBLK / 32];
    int t = threadIdx.x, lane = t & 31, w = t >> 5;
    int i = blockIdx.x * SBLK + t;
    int v = (i < NODES) ? g_cnt[i] : 0;
    if (i < NODES) g_dinv[i] = rsqrtf(g_deg[i] + 1.0f);
    int s = v;
    #pragma unroll
    for (int o = 16; o; o >>= 1) s += __shfl_down_sync(0xffffffffu, s, o);
    if (lane == 0) ws[w] = s;
    __syncthreads();
    if (t < SBLK / 32) {
        int x = ws[t];
        #pragma unroll
        for (int o = 8; o; o >>= 1) x += __shfl_down_sync(0x0000ffffu, x, o);
        if (t == 0) g_bsum[blockIdx.x] = x;
    }
}

// ---------------- scan stage 2 ----------------
__global__ void scan_bsum_kernel() {
    __shared__ int ws[4];
    int t = threadIdx.x, lane = t & 31, w = t >> 5;
    int v = (t < NSB) ? g_bsum[t] : 0;
    int inc = v;
    #pragma unroll
    for (int o = 1; o < 32; o <<= 1) {
        int u = __shfl_up_sync(0xffffffffu, inc, o);
        if (lane >= o) inc += u;
    }
    if (lane == 31) ws[w] = inc;
    __syncthreads();
    int add = 0;
    for (int k = 0; k < w; k++) add += ws[k];
    if (t < NSB) g_boff[t] = add + inc - v;
    if (t == NSB - 1) g_off[NODES] = add + inc;
}

// ---------------- scan stage 3 ----------------
__global__ __launch_bounds__(SBLK) void scan_local_kernel() {
    __shared__ int ws[SBLK / 32];
    int t = threadIdx.x, lane = t & 31, w = t >> 5;
    int i = blockIdx.x * SBLK + t;
    int v = (i < NODES) ? g_cnt[i] : 0;
    int inc = v;
    #pragma unroll
    for (int o = 1; o < 32; o <<= 1) {
        int u = __shfl_up_sync(0xffffffffu, inc, o);
        if (lane >= o) inc += u;
    }
    if (lane == 31) ws[w] = inc;
    __syncthreads();
    int add = g_boff[blockIdx.x];
    for (int k = 0; k < w; k++) add += ws[k];
    if (i < NODES) g_off[i] = add + inc - v;
}

// ---------------- CSR fill (interleaved) ----------------
__global__ void csr_fill_kernel(const int* __restrict__ ei,
                                const float* __restrict__ ew) {
    int e = blockIdx.x * blockDim.x + threadIdx.x;
    if (e >= NE) return;
    int src = ei[e];
    int dst = ei[NE + e];
    int pos = g_off[dst] + atomicAdd(&g_cur[dst], 1);
    float norm = g_dinv[src] * ew[e] * g_dinv[dst];
    g_csr[pos] = make_int2(src, __float_as_int(norm));
}

// ==================== GEMM: g_hw = act(A)[nrows,128] @ W + bias ====================
// 128 threads, 128x128 tile, thread tile 8 rows x 16 cols (8 col-pairs).
// layer >= 0: read g_agg, apply relu((a-mean)*scale) from g_stats[layer] on store.
__global__ __launch_bounds__(128, 2) void gemm_kernel(
    const float* __restrict__ A, const float* __restrict__ W,
    const float* __restrict__ bias, int layer, int nrows)
{
    __shared__ float As[32 * 132];   // [k][row]
    __shared__ float Bs[32 * 128];   // [k][col]
    __shared__ float smean[HID], sscale[HID];
    const bool bn = (layer >= 0);
    const float* __restrict__ src = bn ? (const float*)g_agg : A;
    int tid = threadIdx.x;
    int tr = tid >> 3, tc = tid & 7;
    int row0 = blockIdx.x * 128;

    if (bn && tid < HID) {
        float m = g_stats[layer * 256 + tid] * (1.0f / NODES);
        float v = g_stats[layer * 256 + HID + tid] * (1.0f / NODES) - m * m;
        smean[tid]  = m;
        sscale[tid] = rsqrtf(v + BN_EPS);
    }

    ull acc[8][8];
    #pragma unroll
    for (int i = 0; i < 8; i++)
        #pragma unroll
        for (int p = 0; p < 8; p++) acc[i][p] = 0ull;

    float4 pa[8], pb[8];
    // ---- load chunk 0 into regs ----
    #pragma unroll
    for (int i = 0; i < 8; i++) {
        int slot = tid + i * 128, r = slot >> 3, k4 = slot & 7;
        pa[i] = (row0 + r < nrows)
              ? *(const float4*)(src + (size_t)(row0 + r) * HID + k4 * 4)
              : make_float4(0.f, 0.f, 0.f, 0.f);
    }
    #pragma unroll
    for (int i = 0; i < 8; i++) {
        int slot = tid + i * 128, k = slot >> 5, c4 = slot & 31;
        pb[i] = *(const float4*)(W + (size_t)k * HID + c4 * 4);
    }
    __syncthreads();   // smean/sscale ready

    #pragma unroll 1
    for (int c = 0; c < 4; c++) {
        // ---- store current chunk regs -> smem ----
        #pragma unroll
        for (int i = 0; i < 8; i++) {
            int slot = tid + i * 128, r = slot >> 3, k4 = slot & 7;
            float4 v = pa[i];
            if (bn) {
                int cc = c * 32 + k4 * 4;
                v.x = fmaxf((v.x - smean[cc + 0]) * sscale[cc + 0], 0.f);
                v.y = fmaxf((v.y - smean[cc + 1]) * sscale[cc + 1], 0.f);
                v.z = fmaxf((v.z - smean[cc + 2]) * sscale[cc + 2], 0.f);
                v.w = fmaxf((v.w - smean[cc + 3]) * sscale[cc + 3], 0.f);
            }
            As[(k4 * 4 + 0) * 132 + r] = v.x;
            As[(k4 * 4 + 1) * 132 + r] = v.y;
            As[(k4 * 4 + 2) * 132 + r] = v.z;
            As[(k4 * 4 + 3) * 132 + r] = v.w;
        }
        #pragma unroll
        for (int i = 0; i < 8; i++) {
            int slot = tid + i * 128, k = slot >> 5, c4 = slot & 31;
            *(float4*)(Bs + k * 128 + c4 * 4) = pb[i];
        }
        __syncthreads();
        // ---- prefetch next chunk ----
        if (c < 3) {
            #pragma unroll
            for (int i = 0; i < 8; i++) {
                int slot = tid + i * 128, r = slot >> 3, k4 = slot & 7;
                pa[i] = (row0 + r < nrows)
                      ? *(const float4*)(src + (size_t)(row0 + r) * HID + (c + 1) * 32 + k4 * 4)
                      : make_float4(0.f, 0.f, 0.f, 0.f);
            }
            #pragma unroll
            for (int i = 0; i < 8; i++) {
                int slot = tid + i * 128, k = slot >> 5, c4 = slot & 31;
                pb[i] = *(const float4*)(W + (size_t)((c + 1) * 32 + k) * HID + c4 * 4);
            }
        }
        // ---- compute 32 k-steps ----
        #pragma unroll
        for (int k = 0; k < 32; k++) {
            float4 a0 = *(float4*)(As + k * 132 + tr * 8);
            float4 a1 = *(float4*)(As + k * 132 + tr * 8 + 4);
            const ulonglong2* bq = (const ulonglong2*)(Bs + k * 128 + tc * 16);
            ulonglong2 q0 = bq[0], q1 = bq[1], q2 = bq[2], q3 = bq[3];
            ull bp[8] = { q0.x, q0.y, q1.x, q1.y, q2.x, q2.y, q3.x, q3.y };
            ull ad[8] = { pk2(a0.x, a0.x), pk2(a0.y, a0.y),
                          pk2(a0.z, a0.z), pk2(a0.w, a0.w),
                          pk2(a1.x, a1.x), pk2(a1.y, a1.y),
                          pk2(a1.z, a1.z), pk2(a1.w, a1.w) };
            #pragma unroll
            for (int i = 0; i < 8; i++)
                #pragma unroll
                for (int p = 0; p < 8; p++)
                    fma2(acc[i][p], ad[i], bp[p]);
        }
        __syncthreads();
    }

    float bv[16];
    #pragma unroll
    for (int t = 0; t < 16; t++) bv[t] = bias[tc * 16 + t];
    #pragma unroll
    for (int i = 0; i < 8; i++) {
        int row = row0 + tr * 8 + i;
        if (row >= nrows) continue;
        float2 u[8];
        #pragma unroll
        for (int p = 0; p < 8; p++) u[p] = upk2(acc[i][p]);
        float* o = g_hw + (size_t)row * HID + tc * 16;
        *(float4*)(o)      = make_float4(u[0].x + bv[0],  u[0].y + bv[1],
                                         u[1].x + bv[2],  u[1].y + bv[3]);
        *(float4*)(o + 4)  = make_float4(u[2].x + bv[4],  u[2].y + bv[5],
                                         u[3].x + bv[6],  u[3].y + bv[7]);
        *(float4*)(o + 8)  = make_float4(u[4].x + bv[8],  u[4].y + bv[9],
                                         u[5].x + bv[10], u[5].y + bv[11]);
        *(float4*)(o + 12) = make_float4(u[6].x + bv[12], u[6].y + bv[13],
                                         u[7].x + bv[14], u[7].y + bv[15]);
    }
}

// ---------------- aggregation (warp per node) + BN stats ----------------
__global__ __launch_bounds__(256) void agg_kernel(int layer) {
    __shared__ float bsum[HID];
    __shared__ float bss[HID];
    int tid = threadIdx.x;
    for (int i = tid; i < HID; i += blockDim.x) { bsum[i] = 0.f; bss[i] = 0.f; }
    __syncthreads();

    int lane = tid & 31;
    int wglobal = (blockIdx.x * blockDim.x + tid) >> 5;
    int nwarps  = (gridDim.x * blockDim.x) >> 5;

    float ls0 = 0.f, ls1 = 0.f, ls2 = 0.f, ls3 = 0.f;
    float lq0 = 0.f, lq1 = 0.f, lq2 = 0.f, lq3 = 0.f;

    for (int n = wglobal; n < NODES; n += nwarps) {
        float dv = g_dinv[n];
        float sn = dv * dv;
        float4 a = ((const float4*)(g_hw + (size_t)n * HID))[lane];
        float4 acc = make_float4(a.x * sn, a.y * sn, a.z * sn, a.w * sn);
        int beg = g_off[n], end = g_off[n + 1];
        int i = beg;
        for (; i + 2 <= end; i += 2) {
            int2 e0 = g_csr[i], e1 = g_csr[i + 1];
            float w0 = __int_as_float(e0.y), w1 = __int_as_float(e1.y);
            float4 v0 = ((const float4*)(g_hw + (size_t)e0.x * HID))[lane];
            float4 v1 = ((const float4*)(g_hw + (size_t)e1.x * HID))[lane];
            acc.x += w0 * v0.x + w1 * v1.x;
            acc.y += w0 * v0.y + w1 * v1.y;
            acc.z += w0 * v0.z + w1 * v1.z;
            acc.w += w0 * v0.w + w1 * v1.w;
        }
        if (i < end) {
            int2 e0 = g_csr[i];
            float w = __int_as_float(e0.y);
            float4 v = ((const float4*)(g_hw + (size_t)e0.x * HID))[lane];
            acc.x += w * v.x; acc.y += w * v.y;
            acc.z += w * v.z; acc.w += w * v.w;
        }
        ((float4*)(g_agg + (size_t)n * HID))[lane] = acc;
        ls0 += acc.x; ls1 += acc.y; ls2 += acc.z; ls3 += acc.w;
        lq0 += acc.x * acc.x; lq1 += acc.y * acc.y;
        lq2 += acc.z * acc.z; lq3 += acc.w * acc.w;
    }
    int c = lane * 4;
    atomicAdd(&bsum[c + 0], ls0); atomicAdd(&bsum[c + 1], ls1);
    atomicAdd(&bsum[c + 2], ls2); atomicAdd(&bsum[c + 3], ls3);
    atomicAdd(&bss[c + 0], lq0);  atomicAdd(&bss[c + 1], lq1);
    atomicAdd(&bss[c + 2], lq2);  atomicAdd(&bss[c + 3], lq3);
    __syncthreads();
    for (int i = tid; i < HID; i += blockDim.x) {
        atomicAdd(&g_stats[layer * 256 + i],       bsum[i]);
        atomicAdd(&g_stats[layer * 256 + HID + i], bss[i]);
    }
}

// ---------------- scoring prep (reads g_agg + stats[2] directly) ----------------
__global__ void prep_kernel(const float* __restrict__ l1w,
                            const float* __restrict__ l1b,
                            const int* __restrict__ curr) {
    __shared__ float xs[HID];
    int j = threadIdx.x;   // 128
    int c = *curr;
    float m = g_stats[2 * 256 + j] * (1.0f / NODES);
    float v = g_stats[2 * 256 + HID + j] * (1.0f / NODES) - m * m;
    float sc = rsqrtf(v + BN_EPS);
    xs[j] = fmaxf((g_agg[(size_t)c * HID + j] - m) * sc, 0.f);
    __syncthreads();
    float acc = 0.f;
    #pragma unroll 8
    for (int k = 0; k < HID; k++)
        acc += xs[k] * l1w[(size_t)(HID + k) * HID + j];
    g_base[j] = l1b[j] + acc;
    float we = 0.f;
    #pragma unroll 8
    for (int k = 2 * HID; k < 4 * HID; k++)
        we += l1w[(size_t)k * HID + j];
    g_we[j] = we;
}

// ==================== scoring: BN+ReLU on load (writes h) + GEMM + pooling ====================
__global__ __launch_bounds__(128, 2) void score_kernel(
    const float* __restrict__ W,    // lin1_w rows 0..127
    const float* __restrict__ l2w, const float* __restrict__ l2b,
    const float* __restrict__ ecn, const float* __restrict__ parts,
    float* __restrict__ h, float* __restrict__ out)
{
    __shared__ float As[32 * 132];
    __shared__ float Bs[32 * 128];
    __shared__ float smean[HID], sscale[HID];
    __shared__ float sarr[128];
    __shared__ float pp[NPART];
    int tid = threadIdx.x;
    int tr = tid >> 3, tc = tid & 7;
    int row0 = blockIdx.x * 128;

    if (tid < HID) {
        float m = g_stats[2 * 256 + tid] * (1.0f / NODES);
        float v = g_stats[2 * 256 + HID + tid] * (1.0f / NODES) - m * m;
        smean[tid]  = m;
        sscale[tid] = rsqrtf(v + BN_EPS);
    }

    ull acc[8][8];
    #pragma unroll
    for (int i = 0; i < 8; i++)
        #pragma unroll
        for (int p = 0; p < 8; p++) acc[i][p] = 0ull;

    float4 pa[8], pb[8];
    #pragma unroll
    for (int i = 0; i < 8; i++) {
        int slot = tid + i * 128, r = slot >> 3, k4 = slot & 7;
        pa[i] = (row0 + r < NODES)
              ? *(const float4*)(g_agg + (size_t)(row0 + r) * HID + k4 * 4)
              : make_float4(0.f, 0.f, 0.f, 0.f);
    }
    #pragma unroll
    for (int i = 0; i < 8; i++) {
        int slot = tid + i * 128, k = slot >> 5, c4 = slot & 31;
        pb[i] = *(const float4*)(W + (size_t)k * HID + c4 * 4);
    }
    __syncthreads();

    #pragma unroll 1
    for (int c = 0; c < 4; c++) {
        #pragma unroll
        for (int i = 0; i < 8; i++) {
            int slot = tid + i * 128, r = slot >> 3, k4 = slot & 7;
            float4 v = pa[i];
            int cc = c * 32 + k4 * 4;
            v.x = fmaxf((v.x - smean[cc + 0]) * sscale[cc + 0], 0.f);
            v.y = fmaxf((v.y - smean[cc + 1]) * sscale[cc + 1], 0.f);
            v.z = fmaxf((v.z - smean[cc + 2]) * sscale[cc + 2], 0.f);
            v.w = fmaxf((v.w - smean[cc + 3]) * sscale[cc + 3], 0.f);
            if (row0 + r < NODES)
                *(float4*)(h + (size_t)(row0 + r) * HID + cc) = v;   // final h output
            As[(k4 * 4 + 0) * 132 + r] = v.x;
            As[(k4 * 4 + 1) * 132 + r] = v.y;
            As[(k4 * 4 + 2) * 132 + r] = v.z;
            As[(k4 * 4 + 3) * 132 + r] = v.w;
        }
        #pragma unroll
        for (int i = 0; i < 8; i++) {
            int slot = tid + i * 128, k = slot >> 5, c4 = slot & 31;
            *(float4*)(Bs + k * 128 + c4 * 4) = pb[i];
        }
        __syncthreads();
        if (c < 3) {
            #pragma unroll
            for (int i = 0; i < 8; i++) {
                int slot = tid + i * 128, r = slot >> 3, k4 = slot & 7;
                pa[i] = (row0 + r < NODES)
                      ? *(const float4*)(g_agg + (size_t)(row0 + r) * HID + (c + 1) * 32 + k4 * 4)
                      : make_float4(0.f, 0.f, 0.f, 0.f);
            }
            #pragma unroll
            for (int i = 0; i < 8; i++) {
                int slot = tid + i * 128, k = slot >> 5, c4 = slot & 31;
                pb[i] = *(const float4*)(W + (size_t)((c + 1) * 32 + k) * HID + c4 * 4);
            }
        }
        #pragma unroll
        for (int k = 0; k < 32; k++) {
            float4 a0 = *(float4*)(As + k * 132 + tr * 8);
            float4 a1 = *(float4*)(As + k * 132 + tr * 8 + 4);
            const ulonglong2* bq = (const ulonglong2*)(Bs + k * 128 + tc * 16);
            ulonglong2 q0 = bq[0], q1 = bq[1], q2 = bq[2], q3 = bq[3];
            ull bp[8] = { q0.x, q0.y, q1.x, q1.y, q2.x, q2.y, q3.x, q3.y };
            ull ad[8] = { pk2(a0.x, a0.x), pk2(a0.y, a0.y),
                          pk2(a0.z, a0.z), pk2(a0.w, a0.w),
                          pk2(a1.x, a1.x), pk2(a1.y, a1.y),
                          pk2(a1.z, a1.z), pk2(a1.w, a1.w) };
            #pragma unroll
            for (int i = 0; i < 8; i++)
                #pragma unroll
                for (int p = 0; p < 8; p++)
                    fma2(acc[i][p], ad[i], bp[p]);
        }
        __syncthreads();
    }

    // epilogue: relu(acc + base + e*we) . w2, then partition pooling
    float bb[16], wev[16], w2v[16];
    #pragma unroll
    for (int t = 0; t < 16; t++) {
        int col = tc * 16 + t;
        bb[t]  = g_base[col];
        wev[t] = g_we[col];
        w2v[t] = l2w[col];
    }
    float b2 = l2b[0];
    #pragma unroll
    for (int i = 0; i < 8; i++) {
        int row = row0 + tr * 8 + i;
        float e = (row < NODES) ? ecn[row] : 0.f;
        float s = 0.f;
        #pragma unroll
        for (int p = 0; p < 8; p++) {
            float2 u = upk2(acc[i][p]);
            s += fmaxf(u.x + bb[2 * p]     + e * wev[2 * p],     0.f) * w2v[2 * p];
            s += fmaxf(u.y + bb[2 * p + 1] + e * wev[2 * p + 1], 0.f) * w2v[2 * p + 1];
        }
        s += __shfl_xor_sync(0xffffffffu, s, 1, 8);
        s += __shfl_xor_sync(0xffffffffu, s, 2, 8);
        s += __shfl_xor_sync(0xffffffffu, s, 4, 8);
        if ((tid & 7) == 0) sarr[tr * 8 + i] = (row < NODES) ? (s + b2) : 0.f;
    }
    if (tid < NPART) pp[tid] = 0.f;
    __syncthreads();
    int p = tid & 31, g = tid >> 5;   // 4 groups x 32 rows
    float psum = 0.f;
    for (int r = g * 32; r < g * 32 + 32; r++) {
        int row = row0 + r;
        if (row < NODES) psum += sarr[r] * parts[(size_t)row * NPART + p];
    }
    atomicAdd(&pp[p], psum);
    __syncthreads();
    if (tid < NPART) atomicAdd(&out[tid], pp[tid]);
}

// ---------------- launcher ----------------
extern "C" void kernel_launch(void* const* d_in, const int* in_sizes, int n_in,
                              void* d_out, int out_size) {
    const float* x      = (const float*)d_in[0];
    const int*   ei     = (const int*)d_in[1];
    const float* ew     = (const float*)d_in[2];
    const float* parts  = (const float*)d_in[3];
    // d_in[4] = node_weights (unused by reference)
    const float* ecn    = (const float*)d_in[5];
    const float* conv_w = (const float*)d_in[6];
    const float* conv_b = (const float*)d_in[7];
    const float* l1w    = (const float*)d_in[8];
    const float* l1b    = (const float*)d_in[9];
    const float* l2w    = (const float*)d_in[10];
    const float* l2b    = (const float*)d_in[11];
    const int*   curr   = (const int*)d_in[12];

    float* out = (float*)d_out;          // [0:32) partition scores
    float* h   = out + NPART;            // [32 : 32+N*H) final h

    zero_init_kernel<<<(NODES + 255) / 256, 256>>>(out);
    deg_count_kernel<<<(NE + 255) / 256, 256>>>(ei, ew);
    block_sum_kernel<<<NSB, SBLK>>>();
    scan_bsum_kernel<<<1, 128>>>();
    scan_local_kernel<<<NSB, SBLK>>>();
    csr_fill_kernel<<<(NE + 255) / 256, 256>>>(ei, ew);

    const int gemm_blocks = (NODES + 127) / 128;   // 391
    // layer 0: plain x
    gemm_kernel<<<gemm_blocks, 128>>>(x, conv_w, conv_b, -1, NODES);
    agg_kernel<<<1184, 256>>>(0);
    // layers 1..2: BN+ReLU fused into GEMM A-load (stats computed per block)
    gemm_kernel<<<gemm_blocks, 128>>>(nullptr, conv_w + 1 * HID * HID,
                                      conv_b + 1 * HID, 0, NODES);
    agg_kernel<<<1184, 256>>>(1);
    gemm_kernel<<<gemm_blocks, 128>>>(nullptr, conv_w + 2 * HID * HID,
                                      conv_b + 2 * HID, 1, NODES);
    agg_kernel<<<1184, 256>>>(2);

    prep_kernel<<<1, 128>>>(l1w, l1b, curr);
    score_kernel<<<gemm_blocks, 128>>>(l1w, l2w, l2b, ecn, parts, h, out);
}

// round 5
// speedup vs baseline: 1.3152x; 1.3152x over previous
#include <cuda_runtime.h>

#define NODES 50000
#define NE    800000
#define HID   128
#define NPART 32
#define BN_EPS 1e-5f
#define SBLK  512
#define NSB   ((NODES + SBLK - 1) / SBLK)   // 98

typedef unsigned long long ull;

// ---------------- scratch (device globals; no runtime alloc) ----------------
__device__ float g_deg[NODES];
__device__ int   g_cnt[NODES];
__device__ int   g_off[NODES + 1];
__device__ int   g_cur[NODES];
__device__ float g_dinv[NODES];
__device__ int   g_bsum[NSB];
__device__ int   g_boff[NSB];
__device__ int2  g_csr[NE];                 // {src, float_as_int(norm)}
__device__ float g_hw[NODES * HID];
__device__ float g_agg[NODES * HID];
__device__ float g_stats[3 * 2 * HID];      // per layer: [0:128) sum, [128:256) sumsq
__device__ float g_base[HID];
__device__ float g_we[HID];

// ---------------- f32x2 helpers ----------------
__device__ __forceinline__ ull pk2(float lo, float hi) {
    ull r;
    asm("mov.b64 %0, {%1, %2};" : "=l"(r) : "f"(lo), "f"(hi));
    return r;
}
__device__ __forceinline__ void fma2(ull& d, ull a, ull b) {
    asm("fma.rn.f32x2 %0, %1, %2, %0;" : "+l"(d) : "l"(a), "l"(b));
}
__device__ __forceinline__ float2 upk2(ull v) {
    float2 f;
    asm("mov.b64 {%0, %1}, %2;" : "=f"(f.x), "=f"(f.y) : "l"(v));
    return f;
}

// ---------------- init ----------------
__global__ void zero_init_kernel(float* out) {
    int i = blockIdx.x * blockDim.x + threadIdx.x;
    if (i < NODES) { g_deg[i] = 0.f; g_cnt[i] = 0; g_cur[i] = 0; }
    if (i < NPART) out[i] = 0.f;
    if (i < 3 * 2 * HID) g_stats[i] = 0.f;
}

// ---------------- degree + count ----------------
__global__ void deg_count_kernel(const int* __restrict__ ei,
                                 const float* __restrict__ ew) {
    int e = blockIdx.x * blockDim.x + threadIdx.x;
    if (e >= NE) return;
    int dst = ei[NE + e];
    atomicAdd(&g_deg[dst], ew[e]);
    atomicAdd(&g_cnt[dst], 1);
}

// ---------------- scan stage 1: per-block sums (+ dinv fused) ----------------
__global__ __launch_bounds__(SBLK) void block_sum_kernel() {
    __shared__ int ws[SBLK / 32];
    int t = threadIdx.x, lane = t & 31, w = t >> 5;
    int i = blockIdx.x * SBLK + t;
    int v = (i < NODES) ? g_cnt[i] : 0;
    if (i < NODES) g_dinv[i] = rsqrtf(g_deg[i] + 1.0f);
    int s = v;
    #pragma unroll
    for (int o = 16; o; o >>= 1) s += __shfl_down_sync(0xffffffffu, s, o);
    if (lane == 0) ws[w] = s;
    __syncthreads();
    if (t < SBLK / 32) {
        int x = ws[t];
        #pragma unroll
        for (int o = 8; o; o >>= 1) x += __shfl_down_sync(0x0000ffffu, x, o);
        if (t == 0) g_bsum[blockIdx.x] = x;
    }
}

// ---------------- scan stage 2 ----------------
__global__ void scan_bsum_kernel() {
    __shared__ int ws[4];
    int t = threadIdx.x, lane = t & 31, w = t >> 5;
    int v = (t < NSB) ? g_bsum[t] : 0;
    int inc = v;
    #pragma unroll
    for (int o = 1; o < 32; o <<= 1) {
        int u = __shfl_up_sync(0xffffffffu, inc, o);
        if (lane >= o) inc += u;
    }
    if (lane == 31) ws[w] = inc;
    __syncthreads();
    int add = 0;
    for (int k = 0; k < w; k++) add += ws[k];
    if (t < NSB) g_boff[t] = add + inc - v;
    if (t == NSB - 1) g_off[NODES] = add + inc;
}

// ---------------- scan stage 3 ----------------
__global__ __launch_bounds__(SBLK) void scan_local_kernel() {
    __shared__ int ws[SBLK / 32];
    int t = threadIdx.x, lane = t & 31, w = t >> 5;
    int i = blockIdx.x * SBLK + t;
    int v = (i < NODES) ? g_cnt[i] : 0;
    int inc = v;
    #pragma unroll
    for (int o = 1; o < 32; o <<= 1) {
        int u = __shfl_up_sync(0xffffffffu, inc, o);
        if (lane >= o) inc += u;
    }
    if (lane == 31) ws[w] = inc;
    __syncthreads();
    int add = g_boff[blockIdx.x];
    for (int k = 0; k < w; k++) add += ws[k];
    if (i < NODES) g_off[i] = add + inc - v;
}

// ---------------- CSR fill (interleaved) ----------------
__global__ void csr_fill_kernel(const int* __restrict__ ei,
                                const float* __restrict__ ew) {
    int e = blockIdx.x * blockDim.x + threadIdx.x;
    if (e >= NE) return;
    int src = ei[e];
    int dst = ei[NE + e];
    int pos = g_off[dst] + atomicAdd(&g_cur[dst], 1);
    float norm = g_dinv[src] * ew[e] * g_dinv[dst];
    g_csr[pos] = make_int2(src, __float_as_int(norm));
}

// ==================== GEMM: g_hw = act(A)[nrows,128] @ W + bias ====================
// Round-3 proven shape: 256 threads, 128x128 block tile, 8x8 thread tile,
// f32x2 row-pair accumulators. layer >= 0: read g_agg, apply
// relu((a - mean)*scale) computed per-block from g_stats[layer].
__global__ __launch_bounds__(256) void gemm_kernel(
    const float* __restrict__ A, const float* __restrict__ W,
    const float* __restrict__ bias, int layer, int nrows)
{
    __shared__ float As[32 * 132];   // [k][row], padded
    __shared__ float Bs[32 * 128];   // [k][col]
    __shared__ float smean[HID], sscale[HID];
    const bool bn = (layer >= 0);
    const float* __restrict__ src = bn ? (const float*)g_agg : A;
    int tid = threadIdx.x;
    int tr = tid >> 4, tc = tid & 15;
    int row0 = blockIdx.x * 128;

    if (bn) {
        if (tid < HID) {
            float m = g_stats[layer * 256 + tid] * (1.0f / NODES);
            float v = g_stats[layer * 256 + HID + tid] * (1.0f / NODES) - m * m;
            smean[tid]  = m;
            sscale[tid] = rsqrtf(v + BN_EPS);
        }
        __syncthreads();
    }

    ull acc[4][8];    // row-pairs x 8 cols
    #pragma unroll
    for (int i = 0; i < 4; i++)
        #pragma unroll
        for (int j = 0; j < 8; j++) acc[i][j] = 0ull;

    for (int kc = 0; kc < HID; kc += 32) {
        #pragma unroll
        for (int i = 0; i < 4; i++) {
            int slot = tid + i * 256;
            int r  = slot >> 3;
            int k4 = slot & 7;
            float4 v = make_float4(0.f, 0.f, 0.f, 0.f);
            if (row0 + r < nrows)
                v = *(const float4*)(src + (size_t)(row0 + r) * HID + kc + k4 * 4);
            if (bn) {
                int c = kc + k4 * 4;
                v.x = fmaxf((v.x - smean[c + 0]) * sscale[c + 0], 0.f);
                v.y = fmaxf((v.y - smean[c + 1]) * sscale[c + 1], 0.f);
                v.z = fmaxf((v.z - smean[c + 2]) * sscale[c + 2], 0.f);
                v.w = fmaxf((v.w - smean[c + 3]) * sscale[c + 3], 0.f);
            }
            As[(k4 * 4 + 0) * 132 + r] = v.x;
            As[(k4 * 4 + 1) * 132 + r] = v.y;
            As[(k4 * 4 + 2) * 132 + r] = v.z;
            As[(k4 * 4 + 3) * 132 + r] = v.w;
        }
        #pragma unroll
        for (int i = 0; i < 4; i++) {
            int slot = tid + i * 256;
            int k  = slot >> 5;
            int c4 = slot & 31;
            *(float4*)(Bs + k * 128 + c4 * 4) =
                *(const float4*)(W + (size_t)(kc + k) * HID + c4 * 4);
        }
        __syncthreads();
        #pragma unroll
        for (int k = 0; k < 32; k++) {
            float4 a0 = *(float4*)(As + k * 132 + tr * 8);
            float4 a1 = *(float4*)(As + k * 132 + tr * 8 + 4);
            float4 b0 = *(float4*)(Bs + k * 128 + tc * 8);
            float4 b1 = *(float4*)(Bs + k * 128 + tc * 8 + 4);
            ull ap[4] = { pk2(a0.x, a0.y), pk2(a0.z, a0.w),
                          pk2(a1.x, a1.y), pk2(a1.z, a1.w) };
            ull bd[8] = { pk2(b0.x, b0.x), pk2(b0.y, b0.y),
                          pk2(b0.z, b0.z), pk2(b0.w, b0.w),
                          pk2(b1.x, b1.x), pk2(b1.y, b1.y),
                          pk2(b1.z, b1.z), pk2(b1.w, b1.w) };
            #pragma unroll
            for (int i = 0; i < 4; i++)
                #pragma unroll
                for (int j = 0; j < 8; j++)
                    fma2(acc[i][j], ap[i], bd[j]);
        }
        __syncthreads();
    }
    float bv[8];
    #pragma unroll
    for (int j = 0; j < 8; j++) bv[j] = bias[tc * 8 + j];
    #pragma unroll
    for (int i2 = 0; i2 < 4; i2++) {
        float2 v[8];
        #pragma unroll
        for (int j = 0; j < 8; j++) v[j] = upk2(acc[i2][j]);
        int r0 = row0 + tr * 8 + i2 * 2;
        if (r0 < nrows) {
            float4 o0 = make_float4(v[0].x + bv[0], v[1].x + bv[1],
                                    v[2].x + bv[2], v[3].x + bv[3]);
            float4 o1 = make_float4(v[4].x + bv[4], v[5].x + bv[5],
                                    v[6].x + bv[6], v[7].x + bv[7]);
            *(float4*)(g_hw + (size_t)r0 * HID + tc * 8)     = o0;
            *(float4*)(g_hw + (size_t)r0 * HID + tc * 8 + 4) = o1;
        }
        if (r0 + 1 < nrows) {
            float4 o0 = make_float4(v[0].y + bv[0], v[1].y + bv[1],
                                    v[2].y + bv[2], v[3].y + bv[3]);
            float4 o1 = make_float4(v[4].y + bv[4], v[5].y + bv[5],
                                    v[6].y + bv[6], v[7].y + bv[7]);
            *(float4*)(g_hw + (size_t)(r0 + 1) * HID + tc * 8)     = o0;
            *(float4*)(g_hw + (size_t)(r0 + 1) * HID + tc * 8 + 4) = o1;
        }
    }
}

// ---------------- aggregation (warp per node) + BN stats ----------------
__global__ __launch_bounds__(256) void agg_kernel(int layer) {
    __shared__ float bsum[HID];
    __shared__ float bss[HID];
    int tid = threadIdx.x;
    for (int i = tid; i < HID; i += blockDim.x) { bsum[i] = 0.f; bss[i] = 0.f; }
    __syncthreads();

    int lane = tid & 31;
    int wglobal = (blockIdx.x * blockDim.x + tid) >> 5;
    int nwarps  = (gridDim.x * blockDim.x) >> 5;

    float ls0 = 0.f, ls1 = 0.f, ls2 = 0.f, ls3 = 0.f;
    float lq0 = 0.f, lq1 = 0.f, lq2 = 0.f, lq3 = 0.f;

    for (int n = wglobal; n < NODES; n += nwarps) {
        float dv = g_dinv[n];
        float sn = dv * dv;
        float4 a = ((const float4*)(g_hw + (size_t)n * HID))[lane];
        float4 acc = make_float4(a.x * sn, a.y * sn, a.z * sn, a.w * sn);
        int beg = g_off[n], end = g_off[n + 1];
        int i = beg;
        for (; i + 2 <= end; i += 2) {
            int2 e0 = g_csr[i], e1 = g_csr[i + 1];
            float w0 = __int_as_float(e0.y), w1 = __int_as_float(e1.y);
            float4 v0 = ((const float4*)(g_hw + (size_t)e0.x * HID))[lane];
            float4 v1 = ((const float4*)(g_hw + (size_t)e1.x * HID))[lane];
            acc.x += w0 * v0.x + w1 * v1.x;
            acc.y += w0 * v0.y + w1 * v1.y;
            acc.z += w0 * v0.z + w1 * v1.z;
            acc.w += w0 * v0.w + w1 * v1.w;
        }
        if (i < end) {
            int2 e0 = g_csr[i];
            float w = __int_as_float(e0.y);
            float4 v = ((const float4*)(g_hw + (size_t)e0.x * HID))[lane];
            acc.x += w * v.x; acc.y += w * v.y;
            acc.z += w * v.z; acc.w += w * v.w;
        }
        ((float4*)(g_agg + (size_t)n * HID))[lane] = acc;
        ls0 += acc.x; ls1 += acc.y; ls2 += acc.z; ls3 += acc.w;
        lq0 += acc.x * acc.x; lq1 += acc.y * acc.y;
        lq2 += acc.z * acc.z; lq3 += acc.w * acc.w;
    }
    int c = lane * 4;
    atomicAdd(&bsum[c + 0], ls0); atomicAdd(&bsum[c + 1], ls1);
    atomicAdd(&bsum[c + 2], ls2); atomicAdd(&bsum[c + 3], ls3);
    atomicAdd(&bss[c + 0], lq0);  atomicAdd(&bss[c + 1], lq1);
    atomicAdd(&bss[c + 2], lq2);  atomicAdd(&bss[c + 3], lq3);
    __syncthreads();
    for (int i = tid; i < HID; i += blockDim.x) {
        atomicAdd(&g_stats[layer * 256 + i],       bsum[i]);
        atomicAdd(&g_stats[layer * 256 + HID + i], bss[i]);
    }
}

// ---------------- scoring prep (reads g_agg + stats[2] directly) ----------------
__global__ void prep_kernel(const float* __restrict__ l1w,
                            const float* __restrict__ l1b,
                            const int* __restrict__ curr) {
    __shared__ float xs[HID];
    int j = threadIdx.x;   // 128
    int c = *curr;
    float m = g_stats[2 * 256 + j] * (1.0f / NODES);
    float v = g_stats[2 * 256 + HID + j] * (1.0f / NODES) - m * m;
    float sc = rsqrtf(v + BN_EPS);
    xs[j] = fmaxf((g_agg[(size_t)c * HID + j] - m) * sc, 0.f);
    __syncthreads();
    float acc = 0.f;
    #pragma unroll 8
    for (int k = 0; k < HID; k++)
        acc += xs[k] * l1w[(size_t)(HID + k) * HID + j];
    g_base[j] = l1b[j] + acc;
    float we = 0.f;
    #pragma unroll 8
    for (int k = 2 * HID; k < 4 * HID; k++)
        we += l1w[(size_t)k * HID + j];
    g_we[j] = we;
}

// ==================== scoring: BN+ReLU on A-load (writes h) + GEMM + pooling ====================
// Round-3 proven 256-thread shape.
__global__ __launch_bounds__(256) void score_kernel(
    const float* __restrict__ W,    // lin1_w rows 0..127
    const float* __restrict__ l2w, const float* __restrict__ l2b,
    const float* __restrict__ ecn, const float* __restrict__ parts,
    float* __restrict__ h, float* __restrict__ out)
{
    __shared__ float As[32 * 132];
    __shared__ float Bs[32 * 128];
    __shared__ float smean[HID], sscale[HID];
    __shared__ float sarr[128];
    __shared__ float pp[NPART];
    int tid = threadIdx.x;
    int tr = tid >> 4, tc = tid & 15;
    int row0 = blockIdx.x * 128;

    if (tid < HID) {
        float m = g_stats[2 * 256 + tid] * (1.0f / NODES);
        float v = g_stats[2 * 256 + HID + tid] * (1.0f / NODES) - m * m;
        smean[tid]  = m;
        sscale[tid] = rsqrtf(v + BN_EPS);
    }
    __syncthreads();

    ull acc[4][8];
    #pragma unroll
    for (int i = 0; i < 4; i++)
        #pragma unroll
        for (int j = 0; j < 8; j++) acc[i][j] = 0ull;

    for (int kc = 0; kc < HID; kc += 32) {
        #pragma unroll
        for (int i = 0; i < 4; i++) {
            int slot = tid + i * 256;
            int r  = slot >> 3;
            int k4 = slot & 7;
            float4 v = make_float4(0.f, 0.f, 0.f, 0.f);
            int c = kc + k4 * 4;
            if (row0 + r < NODES) {
                v = *(const float4*)(g_agg + (size_t)(row0 + r) * HID + c);
                v.x = fmaxf((v.x - smean[c + 0]) * sscale[c + 0], 0.f);
                v.y = fmaxf((v.y - smean[c + 1]) * sscale[c + 1], 0.f);
                v.z = fmaxf((v.z - smean[c + 2]) * sscale[c + 2], 0.f);
                v.w = fmaxf((v.w - smean[c + 3]) * sscale[c + 3], 0.f);
                *(float4*)(h + (size_t)(row0 + r) * HID + c) = v;   // final h output
            }
            As[(k4 * 4 + 0) * 132 + r] = v.x;
            As[(k4 * 4 + 1) * 132 + r] = v.y;
            As[(k4 * 4 + 2) * 132 + r] = v.z;
            As[(k4 * 4 + 3) * 132 + r] = v.w;
        }
        #pragma unroll
        for (int i = 0; i < 4; i++) {
            int slot = tid + i * 256;
            int k  = slot >> 5;
            int c4 = slot & 31;
            *(float4*)(Bs + k * 128 + c4 * 4) =
                *(const float4*)(W + (size_t)(kc + k) * HID + c4 * 4);
        }
        __syncthreads();
        #pragma unroll
        for (int k = 0; k < 32; k++) {
            float4 a0 = *(float4*)(As + k * 132 + tr * 8);
            float4 a1 = *(float4*)(As + k * 132 + tr * 8 + 4);
            float4 b0 = *(float4*)(Bs + k * 128 + tc * 8);
            float4 b1 = *(float4*)(Bs + k * 128 + tc * 8 + 4);
            ull ap[4] = { pk2(a0.x, a0.y), pk2(a0.z, a0.w),
                          pk2(a1.x, a1.y), pk2(a1.z, a1.w) };
            ull bd[8] = { pk2(b0.x, b0.x), pk2(b0.y, b0.y),
                          pk2(b0.z, b0.z), pk2(b0.w, b0.w),
                          pk2(b1.x, b1.x), pk2(b1.y, b1.y),
                          pk2(b1.z, b1.z), pk2(b1.w, b1.w) };
            #pragma unroll
            for (int i = 0; i < 4; i++)
                #pragma unroll
                for (int j = 0; j < 8; j++)
                    fma2(acc[i][j], ap[i], bd[j]);
        }
        __syncthreads();
    }

    float w2[8], bb[8], wev[8];
    #pragma unroll
    for (int j = 0; j < 8; j++) {
        w2[j]  = l2w[tc * 8 + j];
        bb[j]  = g_base[tc * 8 + j];
        wev[j] = g_we[tc * 8 + j];
    }
    float b2 = l2b[0];
    #pragma unroll
    for (int i2 = 0; i2 < 4; i2++) {
        float2 v[8];
        #pragma unroll
        for (int j = 0; j < 8; j++) v[j] = upk2(acc[i2][j]);
        #pragma unroll
        for (int half = 0; half < 2; half++) {
            int row = row0 + tr * 8 + i2 * 2 + half;
            float e = (row < NODES) ? ecn[row] : 0.f;
            float s = 0.f;
            #pragma unroll
            for (int j = 0; j < 8; j++) {
                float val = half ? v[j].y : v[j].x;
                float t = val + bb[j] + e * wev[j];
                s += fmaxf(t, 0.f) * w2[j];
            }
            s += __shfl_xor_sync(0xffffffffu, s, 8, 16);
            s += __shfl_xor_sync(0xffffffffu, s, 4, 16);
            s += __shfl_xor_sync(0xffffffffu, s, 2, 16);
            s += __shfl_xor_sync(0xffffffffu, s, 1, 16);
            if (tc == 0) sarr[tr * 8 + i2 * 2 + half] = (row < NODES) ? (s + b2) : 0.f;
        }
    }
    if (tid < NPART) pp[tid] = 0.f;
    __syncthreads();
    int p = tid & 31, g = tid >> 5;
    float psum = 0.f;
    for (int r = g * 16; r < g * 16 + 16; r++) {
        int row = row0 + r;
        if (row < NODES) psum += sarr[r] * parts[(size_t)row * NPART + p];
    }
    atomicAdd(&pp[p], psum);
    __syncthreads();
    if (tid < NPART) atomicAdd(&out[tid], pp[tid]);
}

// ---------------- launcher ----------------
extern "C" void kernel_launch(void* const* d_in, const int* in_sizes, int n_in,
                              void* d_out, int out_size) {
    const float* x      = (const float*)d_in[0];
    const int*   ei     = (const int*)d_in[1];
    const float* ew     = (const float*)d_in[2];
    const float* parts  = (const float*)d_in[3];
    // d_in[4] = node_weights (unused by reference)
    const float* ecn    = (const float*)d_in[5];
    const float* conv_w = (const float*)d_in[6];
    const float* conv_b = (const float*)d_in[7];
    const float* l1w    = (const float*)d_in[8];
    const float* l1b    = (const float*)d_in[9];
    const float* l2w    = (const float*)d_in[10];
    const float* l2b    = (const float*)d_in[11];
    const int*   curr   = (const int*)d_in[12];

    float* out = (float*)d_out;          // [0:32) partition scores
    float* h   = out + NPART;            // [32 : 32+N*H) final h

    zero_init_kernel<<<(NODES + 255) / 256, 256>>>(out);
    deg_count_kernel<<<(NE + 255) / 256, 256>>>(ei, ew);
    block_sum_kernel<<<NSB, SBLK>>>();
    scan_bsum_kernel<<<1, 128>>>();
    scan_local_kernel<<<NSB, SBLK>>>();
    csr_fill_kernel<<<(NE + 255) / 256, 256>>>(ei, ew);

    const int gemm_blocks = (NODES + 127) / 128;   // 391
    // layer 0: plain x
    gemm_kernel<<<gemm_blocks, 256>>>(x, conv_w, conv_b, -1, NODES);
    agg_kernel<<<1184, 256>>>(0);
    // layers 1..2: BN+ReLU fused into GEMM A-load (stats computed per block)
    gemm_kernel<<<gemm_blocks, 256>>>(nullptr, conv_w + 1 * HID * HID,
                                      conv_b + 1 * HID, 0, NODES);
    agg_kernel<<<1184, 256>>>(1);
    gemm_kernel<<<gemm_blocks, 256>>>(nullptr, conv_w + 2 * HID * HID,
                                      conv_b + 2 * HID, 1, NODES);
    agg_kernel<<<1184, 256>>>(2);

    prep_kernel<<<1, 128>>>(l1w, l1b, curr);
    score_kernel<<<gemm_blocks, 256>>>(l1w, l2w, l2b, ecn, parts, h, out);
}

// round 6
// speedup vs baseline: 1.3626x; 1.0360x over previous
#include <cuda_runtime.h>

#define NODES 50000
#define NE    800000
#define HID   128
#define NPART 32
#define BN_EPS 1e-5f
#define SBLK  512
#define NSB   ((NODES + SBLK - 1) / SBLK)   // 98

typedef unsigned long long ull;

// ---------------- scratch (device globals; no runtime alloc) ----------------
__device__ float g_deg[NODES];
__device__ int   g_cnt[NODES];
__device__ int   g_off[NODES + 1];
__device__ int   g_cur[NODES];
__device__ float g_dinv[NODES];
__device__ int   g_bsum[NSB];
__device__ int   g_boff[NSB];
__device__ int2  g_csr[NE];                 // {src, float_as_int(norm)}
__device__ float g_hw[NODES * HID];
__device__ float g_agg[NODES * HID];
__device__ float g_stats[3 * 2 * HID];      // per layer: [0:128) sum, [128:256) sumsq
__device__ float g_base[HID];
__device__ float g_we[HID];

// ---------------- f32x2 helpers ----------------
__device__ __forceinline__ ull pk2(float lo, float hi) {
    ull r;
    asm("mov.b64 %0, {%1, %2};" : "=l"(r) : "f"(lo), "f"(hi));
    return r;
}
__device__ __forceinline__ void fma2(ull& d, ull a, ull b) {
    asm("fma.rn.f32x2 %0, %1, %2, %0;" : "+l"(d) : "l"(a), "l"(b));
}
__device__ __forceinline__ float2 upk2(ull v) {
    float2 f;
    asm("mov.b64 {%0, %1}, %2;" : "=f"(f.x), "=f"(f.y) : "l"(v));
    return f;
}

// ---------------- init ----------------
__global__ void zero_init_kernel(float* out) {
    int i = blockIdx.x * blockDim.x + threadIdx.x;
    if (i < NODES) { g_deg[i] = 0.f; g_cnt[i] = 0; g_cur[i] = 0; }
    if (i < NPART) out[i] = 0.f;
    if (i < 3 * 2 * HID) g_stats[i] = 0.f;
}

// ---------------- degree + count ----------------
__global__ void deg_count_kernel(const int* __restrict__ ei,
                                 const float* __restrict__ ew) {
    int e = blockIdx.x * blockDim.x + threadIdx.x;
    if (e >= NE) return;
    int dst = ei[NE + e];
    atomicAdd(&g_deg[dst], ew[e]);
    atomicAdd(&g_cnt[dst], 1);
}

// ---------------- scan stage 1: per-block sums (+ dinv fused) ----------------
__global__ __launch_bounds__(SBLK) void block_sum_kernel() {
    __shared__ int ws[SBLK / 32];
    int t = threadIdx.x, lane = t & 31, w = t >> 5;
    int i = blockIdx.x * SBLK + t;
    int v = (i < NODES) ? g_cnt[i] : 0;
    if (i < NODES) g_dinv[i] = rsqrtf(g_deg[i] + 1.0f);
    int s = v;
    #pragma unroll
    for (int o = 16; o; o >>= 1) s += __shfl_down_sync(0xffffffffu, s, o);
    if (lane == 0) ws[w] = s;
    __syncthreads();
    if (t < SBLK / 32) {
        int x = ws[t];
        #pragma unroll
        for (int o = 8; o; o >>= 1) x += __shfl_down_sync(0x0000ffffu, x, o);
        if (t == 0) g_bsum[blockIdx.x] = x;
    }
}

// ---------------- scan stage 2 ----------------
__global__ void scan_bsum_kernel() {
    __shared__ int ws[4];
    int t = threadIdx.x, lane = t & 31, w = t >> 5;
    int v = (t < NSB) ? g_bsum[t] : 0;
    int inc = v;
    #pragma unroll
    for (int o = 1; o < 32; o <<= 1) {
        int u = __shfl_up_sync(0xffffffffu, inc, o);
        if (lane >= o) inc += u;
    }
    if (lane == 31) ws[w] = inc;
    __syncthreads();
    int add = 0;
    for (int k = 0; k < w; k++) add += ws[k];
    if (t < NSB) g_boff[t] = add + inc - v;
    if (t == NSB - 1) g_off[NODES] = add + inc;
}

// ---------------- scan stage 3 ----------------
__global__ __launch_bounds__(SBLK) void scan_local_kernel() {
    __shared__ int ws[SBLK / 32];
    int t = threadIdx.x, lane = t & 31, w = t >> 5;
    int i = blockIdx.x * SBLK + t;
    int v = (i < NODES) ? g_cnt[i] : 0;
    int inc = v;
    #pragma unroll
    for (int o = 1; o < 32; o <<= 1) {
        int u = __shfl_up_sync(0xffffffffu, inc, o);
        if (lane >= o) inc += u;
    }
    if (lane == 31) ws[w] = inc;
    __syncthreads();
    int add = g_boff[blockIdx.x];
    for (int k = 0; k < w; k++) add += ws[k];
    if (i < NODES) g_off[i] = add + inc - v;
}

// ---------------- CSR fill (interleaved) ----------------
__global__ void csr_fill_kernel(const int* __restrict__ ei,
                                const float* __restrict__ ew) {
    int e = blockIdx.x * blockDim.x + threadIdx.x;
    if (e >= NE) return;
    int src = ei[e];
    int dst = ei[NE + e];
    int pos = g_off[dst] + atomicAdd(&g_cur[dst], 1);
    float norm = g_dinv[src] * ew[e] * g_dinv[dst];
    g_csr[pos] = make_int2(src, __float_as_int(norm));
}

// ==================== GEMM: g_hw = act(A)[nrows,128] @ W + bias ====================
// Proven shape: 256 threads, 128x128 block tile, 8x8 thread tile, f32x2 pairs.
__global__ __launch_bounds__(256) void gemm_kernel(
    const float* __restrict__ A, const float* __restrict__ W,
    const float* __restrict__ bias, int layer, int nrows)
{
    __shared__ float As[32 * 132];   // [k][row], padded
    __shared__ float Bs[32 * 128];   // [k][col]
    __shared__ float smean[HID], sscale[HID];
    const bool bn = (layer >= 0);
    const float* __restrict__ src = bn ? (const float*)g_agg : A;
    int tid = threadIdx.x;
    int tr = tid >> 4, tc = tid & 15;
    int row0 = blockIdx.x * 128;

    if (bn) {
        if (tid < HID) {
            float m = g_stats[layer * 256 + tid] * (1.0f / NODES);
            float v = g_stats[layer * 256 + HID + tid] * (1.0f / NODES) - m * m;
            smean[tid]  = m;
            sscale[tid] = rsqrtf(v + BN_EPS);
        }
        __syncthreads();
    }

    ull acc[4][8];    // row-pairs x 8 cols
    #pragma unroll
    for (int i = 0; i < 4; i++)
        #pragma unroll
        for (int j = 0; j < 8; j++) acc[i][j] = 0ull;

    for (int kc = 0; kc < HID; kc += 32) {
        #pragma unroll
        for (int i = 0; i < 4; i++) {
            int slot = tid + i * 256;
            int r  = slot >> 3;
            int k4 = slot & 7;
            float4 v = make_float4(0.f, 0.f, 0.f, 0.f);
            if (row0 + r < nrows)
                v = *(const float4*)(src + (size_t)(row0 + r) * HID + kc + k4 * 4);
            if (bn) {
                int c = kc + k4 * 4;
                v.x = fmaxf((v.x - smean[c + 0]) * sscale[c + 0], 0.f);
                v.y = fmaxf((v.y - smean[c + 1]) * sscale[c + 1], 0.f);
                v.z = fmaxf((v.z - smean[c + 2]) * sscale[c + 2], 0.f);
                v.w = fmaxf((v.w - smean[c + 3]) * sscale[c + 3], 0.f);
            }
            As[(k4 * 4 + 0) * 132 + r] = v.x;
            As[(k4 * 4 + 1) * 132 + r] = v.y;
            As[(k4 * 4 + 2) * 132 + r] = v.z;
            As[(k4 * 4 + 3) * 132 + r] = v.w;
        }
        #pragma unroll
        for (int i = 0; i < 4; i++) {
            int slot = tid + i * 256;
            int k  = slot >> 5;
            int c4 = slot & 31;
            *(float4*)(Bs + k * 128 + c4 * 4) =
                *(const float4*)(W + (size_t)(kc + k) * HID + c4 * 4);
        }
        __syncthreads();
        #pragma unroll
        for (int k = 0; k < 32; k++) {
            float4 a0 = *(float4*)(As + k * 132 + tr * 8);
            float4 a1 = *(float4*)(As + k * 132 + tr * 8 + 4);
            float4 b0 = *(float4*)(Bs + k * 128 + tc * 8);
            float4 b1 = *(float4*)(Bs + k * 128 + tc * 8 + 4);
            ull ap[4] = { pk2(a0.x, a0.y), pk2(a0.z, a0.w),
                          pk2(a1.x, a1.y), pk2(a1.z, a1.w) };
            ull bd[8] = { pk2(b0.x, b0.x), pk2(b0.y, b0.y),
                          pk2(b0.z, b0.z), pk2(b0.w, b0.w),
                          pk2(b1.x, b1.x), pk2(b1.y, b1.y),
                          pk2(b1.z, b1.z), pk2(b1.w, b1.w) };
            #pragma unroll
            for (int i = 0; i < 4; i++)
                #pragma unroll
                for (int j = 0; j < 8; j++)
                    fma2(acc[i][j], ap[i], bd[j]);
        }
        __syncthreads();
    }
    float bv[8];
    #pragma unroll
    for (int j = 0; j < 8; j++) bv[j] = bias[tc * 8 + j];
    #pragma unroll
    for (int i2 = 0; i2 < 4; i2++) {
        float2 v[8];
        #pragma unroll
        for (int j = 0; j < 8; j++) v[j] = upk2(acc[i2][j]);
        int r0 = row0 + tr * 8 + i2 * 2;
        if (r0 < nrows) {
            float4 o0 = make_float4(v[0].x + bv[0], v[1].x + bv[1],
                                    v[2].x + bv[2], v[3].x + bv[3]);
            float4 o1 = make_float4(v[4].x + bv[4], v[5].x + bv[5],
                                    v[6].x + bv[6], v[7].x + bv[7]);
            *(float4*)(g_hw + (size_t)r0 * HID + tc * 8)     = o0;
            *(float4*)(g_hw + (size_t)r0 * HID + tc * 8 + 4) = o1;
        }
        if (r0 + 1 < nrows) {
            float4 o0 = make_float4(v[0].y + bv[0], v[1].y + bv[1],
                                    v[2].y + bv[2], v[3].y + bv[3]);
            float4 o1 = make_float4(v[4].y + bv[4], v[5].y + bv[5],
                                    v[6].y + bv[6], v[7].y + bv[7]);
            *(float4*)(g_hw + (size_t)(r0 + 1) * HID + tc * 8)     = o0;
            *(float4*)(g_hw + (size_t)(r0 + 1) * HID + tc * 8 + 4) = o1;
        }
    }
}

// ---------------- aggregation (warp per node) + BN stats ----------------
__global__ __launch_bounds__(256) void agg_kernel(int layer) {
    __shared__ float bsum[HID];
    __shared__ float bss[HID];
    int tid = threadIdx.x;
    for (int i = tid; i < HID; i += blockDim.x) { bsum[i] = 0.f; bss[i] = 0.f; }
    __syncthreads();

    int lane = tid & 31;
    int wglobal = (blockIdx.x * blockDim.x + tid) >> 5;
    int nwarps  = (gridDim.x * blockDim.x) >> 5;

    float ls0 = 0.f, ls1 = 0.f, ls2 = 0.f, ls3 = 0.f;
    float lq0 = 0.f, lq1 = 0.f, lq2 = 0.f, lq3 = 0.f;

    for (int n = wglobal; n < NODES; n += nwarps) {
        float dv = g_dinv[n];
        float sn = dv * dv;
        float4 a = ((const float4*)(g_hw + (size_t)n * HID))[lane];
        float4 acc = make_float4(a.x * sn, a.y * sn, a.z * sn, a.w * sn);
        int beg = g_off[n], end = g_off[n + 1];
        int i = beg;
        for (; i + 2 <= end; i += 2) {
            int2 e0 = g_csr[i], e1 = g_csr[i + 1];
            float w0 = __int_as_float(e0.y), w1 = __int_as_float(e1.y);
            float4 v0 = ((const float4*)(g_hw + (size_t)e0.x * HID))[lane];
            float4 v1 = ((const float4*)(g_hw + (size_t)e1.x * HID))[lane];
            acc.x += w0 * v0.x + w1 * v1.x;
            acc.y += w0 * v0.y + w1 * v1.y;
            acc.z += w0 * v0.z + w1 * v1.z;
            acc.w += w0 * v0.w + w1 * v1.w;
        }
        if (i < end) {
            int2 e0 = g_csr[i];
            float w = __int_as_float(e0.y);
            float4 v = ((const float4*)(g_hw + (size_t)e0.x * HID))[lane];
            acc.x += w * v.x; acc.y += w * v.y;
            acc.z += w * v.z; acc.w += w * v.w;
        }
        ((float4*)(g_agg + (size_t)n * HID))[lane] = acc;
        ls0 += acc.x; ls1 += acc.y; ls2 += acc.z; ls3 += acc.w;
        lq0 += acc.x * acc.x; lq1 += acc.y * acc.y;
        lq2 += acc.z * acc.z; lq3 += acc.w * acc.w;
    }
    int c = lane * 4;
    atomicAdd(&bsum[c + 0], ls0); atomicAdd(&bsum[c + 1], ls1);
    atomicAdd(&bsum[c + 2], ls2); atomicAdd(&bsum[c + 3], ls3);
    atomicAdd(&bss[c + 0], lq0);  atomicAdd(&bss[c + 1], lq1);
    atomicAdd(&bss[c + 2], lq2);  atomicAdd(&bss[c + 3], lq3);
    __syncthreads();
    for (int i = tid; i < HID; i += blockDim.x) {
        atomicAdd(&g_stats[layer * 256 + i],       bsum[i]);
        atomicAdd(&g_stats[layer * 256 + HID + i], bss[i]);
    }
}

// ---------------- scoring prep (reads g_agg + stats[2] directly) ----------------
__global__ void prep_kernel(const float* __restrict__ l1w,
                            const float* __restrict__ l1b,
                            const int* __restrict__ curr) {
    __shared__ float xs[HID];
    int j = threadIdx.x;   // 128
    int c = *curr;
    float m = g_stats[2 * 256 + j] * (1.0f / NODES);
    float v = g_stats[2 * 256 + HID + j] * (1.0f / NODES) - m * m;
    float sc = rsqrtf(v + BN_EPS);
    xs[j] = fmaxf((g_agg[(size_t)c * HID + j] - m) * sc, 0.f);
    __syncthreads();
    float acc = 0.f;
    #pragma unroll 8
    for (int k = 0; k < HID; k++)
        acc += xs[k] * l1w[(size_t)(HID + k) * HID + j];
    g_base[j] = l1b[j] + acc;
    float we = 0.f;
    #pragma unroll 8
    for (int k = 2 * HID; k < 4 * HID; k++)
        we += l1w[(size_t)k * HID + j];
    g_we[j] = we;
}

// ==================== scoring: BN+ReLU on A-load (writes h) + GEMM + pooling ====================
__global__ __launch_bounds__(256) void score_kernel(
    const float* __restrict__ W,    // lin1_w rows 0..127
    const float* __restrict__ l2w, const float* __restrict__ l2b,
    const float* __restrict__ ecn, const float* __restrict__ parts,
    float* __restrict__ h, float* __restrict__ out)
{
    __shared__ float As[32 * 132];
    __shared__ float Bs[32 * 128];
    __shared__ float smean[HID], sscale[HID];
    __shared__ float sarr[128];
    __shared__ float pp[NPART];
    int tid = threadIdx.x;
    int tr = tid >> 4, tc = tid & 15;
    int row0 = blockIdx.x * 128;

    if (tid < HID) {
        float m = g_stats[2 * 256 + tid] * (1.0f / NODES);
        float v = g_stats[2 * 256 + HID + tid] * (1.0f / NODES) - m * m;
        smean[tid]  = m;
        sscale[tid] = rsqrtf(v + BN_EPS);
    }
    __syncthreads();

    ull acc[4][8];
    #pragma unroll
    for (int i = 0; i < 4; i++)
        #pragma unroll
        for (int j = 0; j < 8; j++) acc[i][j] = 0ull;

    for (int kc = 0; kc < HID; kc += 32) {
        #pragma unroll
        for (int i = 0; i < 4; i++) {
            int slot = tid + i * 256;
            int r  = slot >> 3;
            int k4 = slot & 7;
            float4 v = make_float4(0.f, 0.f, 0.f, 0.f);
            int c = kc + k4 * 4;
            if (row0 + r < NODES) {
                v = *(const float4*)(g_agg + (size_t)(row0 + r) * HID + c);
                v.x = fmaxf((v.x - smean[c + 0]) * sscale[c + 0], 0.f);
                v.y = fmaxf((v.y - smean[c + 1]) * sscale[c + 1], 0.f);
                v.z = fmaxf((v.z - smean[c + 2]) * sscale[c + 2], 0.f);
                v.w = fmaxf((v.w - smean[c + 3]) * sscale[c + 3], 0.f);
                *(float4*)(h + (size_t)(row0 + r) * HID + c) = v;   // final h output
            }
            As[(k4 * 4 + 0) * 132 + r] = v.x;
            As[(k4 * 4 + 1) * 132 + r] = v.y;
            As[(k4 * 4 + 2) * 132 + r] = v.z;
            As[(k4 * 4 + 3) * 132 + r] = v.w;
        }
        #pragma unroll
        for (int i = 0; i < 4; i++) {
            int slot = tid + i * 256;
            int k  = slot >> 5;
            int c4 = slot & 31;
            *(float4*)(Bs + k * 128 + c4 * 4) =
                *(const float4*)(W + (size_t)(kc + k) * HID + c4 * 4);
        }
        __syncthreads();
        #pragma unroll
        for (int k = 0; k < 32; k++) {
            float4 a0 = *(float4*)(As + k * 132 + tr * 8);
            float4 a1 = *(float4*)(As + k * 132 + tr * 8 + 4);
            float4 b0 = *(float4*)(Bs + k * 128 + tc * 8);
            float4 b1 = *(float4*)(Bs + k * 128 + tc * 8 + 4);
            ull ap[4] = { pk2(a0.x, a0.y), pk2(a0.z, a0.w),
                          pk2(a1.x, a1.y), pk2(a1.z, a1.w) };
            ull bd[8] = { pk2(b0.x, b0.x), pk2(b0.y, b0.y),
                          pk2(b0.z, b0.z), pk2(b0.w, b0.w),
                          pk2(b1.x, b1.x), pk2(b1.y, b1.y),
                          pk2(b1.z, b1.z), pk2(b1.w, b1.w) };
            #pragma unroll
            for (int i = 0; i < 4; i++)
                #pragma unroll
                for (int j = 0; j < 8; j++)
                    fma2(acc[i][j], ap[i], bd[j]);
        }
        __syncthreads();
    }

    float w2[8], bb[8], wev[8];
    #pragma unroll
    for (int j = 0; j < 8; j++) {
        w2[j]  = l2w[tc * 8 + j];
        bb[j]  = g_base[tc * 8 + j];
        wev[j] = g_we[tc * 8 + j];
    }
    float b2 = l2b[0];
    #pragma unroll
    for (int i2 = 0; i2 < 4; i2++) {
        float2 v[8];
        #pragma unroll
        for (int j = 0; j < 8; j++) v[j] = upk2(acc[i2][j]);
        #pragma unroll
        for (int half = 0; half < 2; half++) {
            int row = row0 + tr * 8 + i2 * 2 + half;
            float e = (row < NODES) ? ecn[row] : 0.f;
            float s = 0.f;
            #pragma unroll
            for (int j = 0; j < 8; j++) {
                float val = half ? v[j].y : v[j].x;
                float t = val + bb[j] + e * wev[j];
                s += fmaxf(t, 0.f) * w2[j];
            }
            s += __shfl_xor_sync(0xffffffffu, s, 8, 16);
            s += __shfl_xor_sync(0xffffffffu, s, 4, 16);
            s += __shfl_xor_sync(0xffffffffu, s, 2, 16);
            s += __shfl_xor_sync(0xffffffffu, s, 1, 16);
            if (tc == 0) sarr[tr * 8 + i2 * 2 + half] = (row < NODES) ? (s + b2) : 0.f;
        }
    }
    if (tid < NPART) pp[tid] = 0.f;
    __syncthreads();
    int p = tid & 31, g = tid >> 5;
    float psum = 0.f;
    for (int r = g * 16; r < g * 16 + 16; r++) {
        int row = row0 + r;
        if (row < NODES) psum += sarr[r] * parts[(size_t)row * NPART + p];
    }
    atomicAdd(&pp[p], psum);
    __syncthreads();
    if (tid < NPART) atomicAdd(&out[tid], pp[tid]);
}

// ---------------- launcher ----------------
// Fork-join: gemm0 (depends only on x) runs concurrently with the CSR-build
// chain. Streams/events are created per call and intentionally NOT destroyed
// (2 calls total; destroying a stream participating in capture is risky).
extern "C" void kernel_launch(void* const* d_in, const int* in_sizes, int n_in,
                              void* d_out, int out_size) {
    const float* x      = (const float*)d_in[0];
    const int*   ei     = (const int*)d_in[1];
    const float* ew     = (const float*)d_in[2];
    const float* parts  = (const float*)d_in[3];
    // d_in[4] = node_weights (unused by reference)
    const float* ecn    = (const float*)d_in[5];
    const float* conv_w = (const float*)d_in[6];
    const float* conv_b = (const float*)d_in[7];
    const float* l1w    = (const float*)d_in[8];
    const float* l1b    = (const float*)d_in[9];
    const float* l2w    = (const float*)d_in[10];
    const float* l2b    = (const float*)d_in[11];
    const int*   curr   = (const int*)d_in[12];

    float* out = (float*)d_out;          // [0:32) partition scores
    float* h   = out + NPART;            // [32 : 32+N*H) final h

    cudaStream_t sG;
    cudaStreamCreateWithFlags(&sG, cudaStreamNonBlocking);
    cudaEvent_t evFork, evJoin;
    cudaEventCreateWithFlags(&evFork, cudaEventDisableTiming);
    cudaEventCreateWithFlags(&evJoin, cudaEventDisableTiming);

    const int gemm_blocks = (NODES + 127) / 128;   // 391

    // fork sG off the (captured) default stream
    cudaEventRecord(evFork, 0);
    cudaStreamWaitEvent(sG, evFork, 0);

    // ---- setup chain on default stream ----
    zero_init_kernel<<<(NODES + 255) / 256, 256>>>(out);
    deg_count_kernel<<<(NE + 255) / 256, 256>>>(ei, ew);
    block_sum_kernel<<<NSB, SBLK>>>();
    // ---- gemm0 on sG, concurrent with setup (4th launch -> ncu target) ----
    gemm_kernel<<<gemm_blocks, 256, 0, sG>>>(x, conv_w, conv_b, -1, NODES);
    scan_bsum_kernel<<<1, 128>>>();
    scan_local_kernel<<<NSB, SBLK>>>();
    csr_fill_kernel<<<(NE + 255) / 256, 256>>>(ei, ew);

    // join: agg0 needs csr (default) + g_hw (sG) + zeroed stats (default)
    cudaEventRecord(evJoin, sG);
    cudaStreamWaitEvent(0, evJoin, 0);

    agg_kernel<<<1184, 256>>>(0);
    gemm_kernel<<<gemm_blocks, 256>>>(nullptr, conv_w + 1 * HID * HID,
                                      conv_b + 1 * HID, 0, NODES);
    agg_kernel<<<1184, 256>>>(1);
    gemm_kernel<<<gemm_blocks, 256>>>(nullptr, conv_w + 2 * HID * HID,
                                      conv_b + 2 * HID, 1, NODES);
    agg_kernel<<<1184, 256>>>(2);

    prep_kernel<<<1, 128>>>(l1w, l1b, curr);
    score_kernel<<<gemm_blocks, 256>>>(l1w, l2w, l2b, ecn, parts, h, out);
}

// round 7
// speedup vs baseline: 1.4358x; 1.0537x over previous
#include <cuda_runtime.h>

#define NODES 50000
#define NE    800000
#define HID   128
#define NPART 32
#define BN_EPS 1e-5f
#define SBLK  512
#define NSB   ((NODES + SBLK - 1) / SBLK)   // 98

typedef unsigned long long ull;

// ---------------- scratch (device globals; no runtime alloc) ----------------
__device__ float g_deg[NODES];
__device__ int   g_cnt[NODES];
__device__ int   g_off[NODES + 1];
__device__ int   g_cur[NODES];
__device__ float g_dinv[NODES];
__device__ int   g_bsum[NSB];
__device__ int   g_boff[NSB];
__device__ int2  g_csr[NE];                 // {src, float_as_int(norm)}
__device__ float g_hw[NODES * HID];
__device__ float g_agg[NODES * HID];
__device__ float g_stats[3 * 2 * HID];      // per layer: [0:128) sum, [128:256) sumsq
__device__ float g_base[HID];
__device__ float g_we[HID];

// ---------------- f32x2 helpers ----------------
__device__ __forceinline__ ull pk2(float lo, float hi) {
    ull r;
    asm("mov.b64 %0, {%1, %2};" : "=l"(r) : "f"(lo), "f"(hi));
    return r;
}
__device__ __forceinline__ void fma2(ull& d, ull a, ull b) {
    asm("fma.rn.f32x2 %0, %1, %2, %0;" : "+l"(d) : "l"(a), "l"(b));
}
__device__ __forceinline__ float2 upk2(ull v) {
    float2 f;
    asm("mov.b64 {%0, %1}, %2;" : "=f"(f.x), "=f"(f.y) : "l"(v));
    return f;
}
// ---------------- cp.async helpers ----------------
__device__ __forceinline__ void cpasync16(void* smem_ptr, const void* gptr) {
    unsigned s = (unsigned)__cvta_generic_to_shared(smem_ptr);
    asm volatile("cp.async.cg.shared.global [%0], [%1], 16;"
                 :: "r"(s), "l"(gptr) : "memory");
}
__device__ __forceinline__ void cpasync_commit() {
    asm volatile("cp.async.commit_group;" ::: "memory");
}
__device__ __forceinline__ void cpasync_wait_all() {
    asm volatile("cp.async.wait_group 0;" ::: "memory");
}

// ---------------- init ----------------
__global__ void zero_init_kernel(float* out) {
    int i = blockIdx.x * blockDim.x + threadIdx.x;
    if (i < NODES) { g_deg[i] = 0.f; g_cnt[i] = 0; g_cur[i] = 0; }
    if (i < NPART) out[i] = 0.f;
    if (i < 3 * 2 * HID) g_stats[i] = 0.f;
}

// ---------------- degree + count ----------------
__global__ void deg_count_kernel(const int* __restrict__ ei,
                                 const float* __restrict__ ew) {
    int e = blockIdx.x * blockDim.x + threadIdx.x;
    if (e >= NE) return;
    int dst = ei[NE + e];
    atomicAdd(&g_deg[dst], ew[e]);
    atomicAdd(&g_cnt[dst], 1);
}

// ---------------- scan stage 1: per-block sums (+ dinv fused) ----------------
__global__ __launch_bounds__(SBLK) void block_sum_kernel() {
    __shared__ int ws[SBLK / 32];
    int t = threadIdx.x, lane = t & 31, w = t >> 5;
    int i = blockIdx.x * SBLK + t;
    int v = (i < NODES) ? g_cnt[i] : 0;
    if (i < NODES) g_dinv[i] = rsqrtf(g_deg[i] + 1.0f);
    int s = v;
    #pragma unroll
    for (int o = 16; o; o >>= 1) s += __shfl_down_sync(0xffffffffu, s, o);
    if (lane == 0) ws[w] = s;
    __syncthreads();
    if (t < SBLK / 32) {
        int x = ws[t];
        #pragma unroll
        for (int o = 8; o; o >>= 1) x += __shfl_down_sync(0x0000ffffu, x, o);
        if (t == 0) g_bsum[blockIdx.x] = x;
    }
}

// ---------------- scan stage 2 ----------------
__global__ void scan_bsum_kernel() {
    __shared__ int ws[4];
    int t = threadIdx.x, lane = t & 31, w = t >> 5;
    int v = (t < NSB) ? g_bsum[t] : 0;
    int inc = v;
    #pragma unroll
    for (int o = 1; o < 32; o <<= 1) {
        int u = __shfl_up_sync(0xffffffffu, inc, o);
        if (lane >= o) inc += u;
    }
    if (lane == 31) ws[w] = inc;
    __syncthreads();
    int add = 0;
    for (int k = 0; k < w; k++) add += ws[k];
    if (t < NSB) g_boff[t] = add + inc - v;
    if (t == NSB - 1) g_off[NODES] = add + inc;
}

// ---------------- scan stage 3 ----------------
__global__ __launch_bounds__(SBLK) void scan_local_kernel() {
    __shared__ int ws[SBLK / 32];
    int t = threadIdx.x, lane = t & 31, w = t >> 5;
    int i = blockIdx.x * SBLK + t;
    int v = (i < NODES) ? g_cnt[i] : 0;
    int inc = v;
    #pragma unroll
    for (int o = 1; o < 32; o <<= 1) {
        int u = __shfl_up_sync(0xffffffffu, inc, o);
        if (lane >= o) inc += u;
    }
    if (lane == 31) ws[w] = inc;
    __syncthreads();
    int add = g_boff[blockIdx.x];
    for (int k = 0; k < w; k++) add += ws[k];
    if (i < NODES) g_off[i] = add + inc - v;
}

// ---------------- CSR fill (interleaved) ----------------
__global__ void csr_fill_kernel(const int* __restrict__ ei,
                                const float* __restrict__ ew) {
    int e = blockIdx.x * blockDim.x + threadIdx.x;
    if (e >= NE) return;
    int src = ei[e];
    int dst = ei[NE + e];
    int pos = g_off[dst] + atomicAdd(&g_cur[dst], 1);
    float norm = g_dinv[src] * ew[e] * g_dinv[dst];
    g_csr[pos] = make_int2(src, __float_as_int(norm));
}

// ==================== pipelined GEMM: g_hw = act(A)[nrows,128] @ W + bias ====================
// 256 threads, 128x128 block tile, 8x8 thread tile, f32x2 accumulators.
// Double-buffered smem, K-chunk=16. B via cp.async (1 chunk ahead);
// A via LDG->reg (2 chunks ahead) -> BN transform -> STS.
#define KC 16
#define NCHUNK (HID / KC)   // 8
__global__ __launch_bounds__(256) void gemm_kernel(
    const float* __restrict__ A, const float* __restrict__ W,
    const float* __restrict__ bias, int layer, int nrows)
{
    __shared__ float As[2][KC * 132];   // [k][row], padded
    __shared__ float Bs[2][KC * 128];   // [k][col]
    __shared__ float smean[HID], sscale[HID];
    const bool bn = (layer >= 0);
    const float* __restrict__ src = bn ? (const float*)g_agg : A;
    int tid = threadIdx.x;
    int tr = tid >> 4, tc = tid & 15;
    int row0 = blockIdx.x * 128;

    if (bn && tid < HID) {
        float m = g_stats[layer * 256 + tid] * (1.0f / NODES);
        float v = g_stats[layer * 256 + HID + tid] * (1.0f / NODES) - m * m;
        smean[tid]  = m;
        sscale[tid] = rsqrtf(v + BN_EPS);
    }

    // A-load mapping: slot = tid + i*256 (i=0,1); r = slot>>2 (0..127), k4 = slot&3
    int rA[2], k4A[2];
    bool okA[2];
    #pragma unroll
    for (int i = 0; i < 2; i++) {
        int slot = tid + i * 256;
        rA[i]  = slot >> 2;
        k4A[i] = slot & 3;
        okA[i] = (row0 + rA[i]) < nrows;
    }
    // B cp.async mapping: slot = tid + i*256; k = slot>>5 (0..15), c4 = slot&31
    int kB[2], c4B[2];
    #pragma unroll
    for (int i = 0; i < 2; i++) {
        int slot = tid + i * 256;
        kB[i]  = slot >> 5;
        c4B[i] = slot & 31;
    }

    ull acc[4][8];
    #pragma unroll
    for (int i = 0; i < 4; i++)
        #pragma unroll
        for (int j = 0; j < 8; j++) acc[i][j] = 0ull;

    float4 pa[2];
    // ---- prologue: chunk 0 ----
    #pragma unroll
    for (int i = 0; i < 2; i++)
        pa[i] = okA[i]
              ? *(const float4*)(src + (size_t)(row0 + rA[i]) * HID + k4A[i] * 4)
              : make_float4(0.f, 0.f, 0.f, 0.f);
    #pragma unroll
    for (int i = 0; i < 2; i++)
        cpasync16(&Bs[0][kB[i] * 128 + c4B[i] * 4],
                  W + (size_t)kB[i] * HID + c4B[i] * 4);
    cpasync_commit();
    __syncthreads();   // smean/sscale visible
    // STS chunk 0 (with transform)
    #pragma unroll
    for (int i = 0; i < 2; i++) {
        float v4[4] = { pa[i].x, pa[i].y, pa[i].z, pa[i].w };
        #pragma unroll
        for (int j = 0; j < 4; j++) {
            float v = v4[j];
            if (bn) {
                int col = k4A[i] * 4 + j;
                v = fmaxf((v - smean[col]) * sscale[col], 0.f);
            }
            As[0][(k4A[i] * 4 + j) * 132 + rA[i]] = v;
        }
    }
    // LDG chunk 1
    #pragma unroll
    for (int i = 0; i < 2; i++)
        pa[i] = okA[i]
              ? *(const float4*)(src + (size_t)(row0 + rA[i]) * HID + KC + k4A[i] * 4)
              : make_float4(0.f, 0.f, 0.f, 0.f);

    // ---- main pipeline ----
    #pragma unroll 1
    for (int c = 0; c < NCHUNK; c++) {
        cpasync_wait_all();     // B[c] ready (issued 1 iter ago)
        __syncthreads();        // As[c&1] visible; old buffers free
        int nb = (c + 1) & 1;
        if (c + 1 < NCHUNK) {
            #pragma unroll
            for (int i = 0; i < 2; i++)
                cpasync16(&Bs[nb][kB[i] * 128 + c4B[i] * 4],
                          W + (size_t)((c + 1) * KC + kB[i]) * HID + c4B[i] * 4);
            cpasync_commit();
            #pragma unroll
            for (int i = 0; i < 2; i++) {
                float v4[4] = { pa[i].x, pa[i].y, pa[i].z, pa[i].w };
                #pragma unroll
                for (int j = 0; j < 4; j++) {
                    float v = v4[j];
                    if (bn) {
                        int col = (c + 1) * KC + k4A[i] * 4 + j;
                        v = fmaxf((v - smean[col]) * sscale[col], 0.f);
                    }
                    As[nb][(k4A[i] * 4 + j) * 132 + rA[i]] = v;
                }
            }
        }
        if (c + 2 < NCHUNK) {
            #pragma unroll
            for (int i = 0; i < 2; i++)
                pa[i] = okA[i]
                      ? *(const float4*)(src + (size_t)(row0 + rA[i]) * HID
                                         + (c + 2) * KC + k4A[i] * 4)
                      : make_float4(0.f, 0.f, 0.f, 0.f);
        }
        const float* as = As[c & 1];
        const float* bs = Bs[c & 1];
        #pragma unroll
        for (int k = 0; k < KC; k++) {
            float4 a0 = *(const float4*)(as + k * 132 + tr * 8);
            float4 a1 = *(const float4*)(as + k * 132 + tr * 8 + 4);
            float4 b0 = *(const float4*)(bs + k * 128 + tc * 8);
            float4 b1 = *(const float4*)(bs + k * 128 + tc * 8 + 4);
            ull ap[4] = { pk2(a0.x, a0.y), pk2(a0.z, a0.w),
                          pk2(a1.x, a1.y), pk2(a1.z, a1.w) };
            ull bd[8] = { pk2(b0.x, b0.x), pk2(b0.y, b0.y),
                          pk2(b0.z, b0.z), pk2(b0.w, b0.w),
                          pk2(b1.x, b1.x), pk2(b1.y, b1.y),
                          pk2(b1.z, b1.z), pk2(b1.w, b1.w) };
            #pragma unroll
            for (int i = 0; i < 4; i++)
                #pragma unroll
                for (int j = 0; j < 8; j++)
                    fma2(acc[i][j], ap[i], bd[j]);
        }
    }

    float bv[8];
    #pragma unroll
    for (int j = 0; j < 8; j++) bv[j] = bias[tc * 8 + j];
    #pragma unroll
    for (int i2 = 0; i2 < 4; i2++) {
        float2 v[8];
        #pragma unroll
        for (int j = 0; j < 8; j++) v[j] = upk2(acc[i2][j]);
        int r0 = row0 + tr * 8 + i2 * 2;
        if (r0 < nrows) {
            float4 o0 = make_float4(v[0].x + bv[0], v[1].x + bv[1],
                                    v[2].x + bv[2], v[3].x + bv[3]);
            float4 o1 = make_float4(v[4].x + bv[4], v[5].x + bv[5],
                                    v[6].x + bv[6], v[7].x + bv[7]);
            *(float4*)(g_hw + (size_t)r0 * HID + tc * 8)     = o0;
            *(float4*)(g_hw + (size_t)r0 * HID + tc * 8 + 4) = o1;
        }
        if (r0 + 1 < nrows) {
            float4 o0 = make_float4(v[0].y + bv[0], v[1].y + bv[1],
                                    v[2].y + bv[2], v[3].y + bv[3]);
            float4 o1 = make_float4(v[4].y + bv[4], v[5].y + bv[5],
                                    v[6].y + bv[6], v[7].y + bv[7]);
            *(float4*)(g_hw + (size_t)(r0 + 1) * HID + tc * 8)     = o0;
            *(float4*)(g_hw + (size_t)(r0 + 1) * HID + tc * 8 + 4) = o1;
        }
    }
}

// ---------------- aggregation (warp per node) + BN stats ----------------
__global__ __launch_bounds__(256) void agg_kernel(int layer) {
    __shared__ float bsum[HID];
    __shared__ float bss[HID];
    int tid = threadIdx.x;
    for (int i = tid; i < HID; i += blockDim.x) { bsum[i] = 0.f; bss[i] = 0.f; }
    __syncthreads();

    int lane = tid & 31;
    int wglobal = (blockIdx.x * blockDim.x + tid) >> 5;
    int nwarps  = (gridDim.x * blockDim.x) >> 5;

    float ls0 = 0.f, ls1 = 0.f, ls2 = 0.f, ls3 = 0.f;
    float lq0 = 0.f, lq1 = 0.f, lq2 = 0.f, lq3 = 0.f;

    for (int n = wglobal; n < NODES; n += nwarps) {
        float dv = g_dinv[n];
        float sn = dv * dv;
        float4 a = ((const float4*)(g_hw + (size_t)n * HID))[lane];
        float4 acc = make_float4(a.x * sn, a.y * sn, a.z * sn, a.w * sn);
        int beg = g_off[n], end = g_off[n + 1];
        int i = beg;
        for (; i + 2 <= end; i += 2) {
            int2 e0 = g_csr[i], e1 = g_csr[i + 1];
            float w0 = __int_as_float(e0.y), w1 = __int_as_float(e1.y);
            float4 v0 = ((const float4*)(g_hw + (size_t)e0.x * HID))[lane];
            float4 v1 = ((const float4*)(g_hw + (size_t)e1.x * HID))[lane];
            acc.x += w0 * v0.x + w1 * v1.x;
            acc.y += w0 * v0.y + w1 * v1.y;
            acc.z += w0 * v0.z + w1 * v1.z;
            acc.w += w0 * v0.w + w1 * v1.w;
        }
        if (i < end) {
            int2 e0 = g_csr[i];
            float w = __int_as_float(e0.y);
            float4 v = ((const float4*)(g_hw + (size_t)e0.x * HID))[lane];
            acc.x += w * v.x; acc.y += w * v.y;
            acc.z += w * v.z; acc.w += w * v.w;
        }
        ((float4*)(g_agg + (size_t)n * HID))[lane] = acc;
        ls0 += acc.x; ls1 += acc.y; ls2 += acc.z; ls3 += acc.w;
        lq0 += acc.x * acc.x; lq1 += acc.y * acc.y;
        lq2 += acc.z * acc.z; lq3 += acc.w * acc.w;
    }
    int c = lane * 4;
    atomicAdd(&bsum[c + 0], ls0); atomicAdd(&bsum[c + 1], ls1);
    atomicAdd(&bsum[c + 2], ls2); atomicAdd(&bsum[c + 3], ls3);
    atomicAdd(&bss[c + 0], lq0);  atomicAdd(&bss[c + 1], lq1);
    atomicAdd(&bss[c + 2], lq2);  atomicAdd(&bss[c + 3], lq3);
    __syncthreads();
    for (int i = tid; i < HID; i += blockDim.x) {
        atomicAdd(&g_stats[layer * 256 + i],       bsum[i]);
        atomicAdd(&g_stats[layer * 256 + HID + i], bss[i]);
    }
}

// ---------------- scoring prep (reads g_agg + stats[2] directly) ----------------
__global__ void prep_kernel(const float* __restrict__ l1w,
                            const float* __restrict__ l1b,
                            const int* __restrict__ curr) {
    __shared__ float xs[HID];
    int j = threadIdx.x;   // 128
    int c = *curr;
    float m = g_stats[2 * 256 + j] * (1.0f / NODES);
    float v = g_stats[2 * 256 + HID + j] * (1.0f / NODES) - m * m;
    float sc = rsqrtf(v + BN_EPS);
    xs[j] = fmaxf((g_agg[(size_t)c * HID + j] - m) * sc, 0.f);
    __syncthreads();
    float acc = 0.f;
    #pragma unroll 8
    for (int k = 0; k < HID; k++)
        acc += xs[k] * l1w[(size_t)(HID + k) * HID + j];
    g_base[j] = l1b[j] + acc;
    float we = 0.f;
    #pragma unroll 8
    for (int k = 2 * HID; k < 4 * HID; k++)
        we += l1w[(size_t)k * HID + j];
    g_we[j] = we;
}

// ==================== scoring: BN+ReLU on A-load (writes h) + GEMM + pooling ====================
__global__ __launch_bounds__(256) void score_kernel(
    const float* __restrict__ W,    // lin1_w rows 0..127
    const float* __restrict__ l2w, const float* __restrict__ l2b,
    const float* __restrict__ ecn, const float* __restrict__ parts,
    float* __restrict__ h, float* __restrict__ out)
{
    __shared__ float As[32 * 132];
    __shared__ float Bs[32 * 128];
    __shared__ float smean[HID], sscale[HID];
    __shared__ float sarr[128];
    __shared__ float pp[NPART];
    int tid = threadIdx.x;
    int tr = tid >> 4, tc = tid & 15;
    int row0 = blockIdx.x * 128;

    if (tid < HID) {
        float m = g_stats[2 * 256 + tid] * (1.0f / NODES);
        float v = g_stats[2 * 256 + HID + tid] * (1.0f / NODES) - m * m;
        smean[tid]  = m;
        sscale[tid] = rsqrtf(v + BN_EPS);
    }
    __syncthreads();

    ull acc[4][8];
    #pragma unroll
    for (int i = 0; i < 4; i++)
        #pragma unroll
        for (int j = 0; j < 8; j++) acc[i][j] = 0ull;

    for (int kc = 0; kc < HID; kc += 32) {
        #pragma unroll
        for (int i = 0; i < 4; i++) {
            int slot = tid + i * 256;
            int r  = slot >> 3;
            int k4 = slot & 7;
            float4 v = make_float4(0.f, 0.f, 0.f, 0.f);
            int c = kc + k4 * 4;
            if (row0 + r < NODES) {
                v = *(const float4*)(g_agg + (size_t)(row0 + r) * HID + c);
                v.x = fmaxf((v.x - smean[c + 0]) * sscale[c + 0], 0.f);
                v.y = fmaxf((v.y - smean[c + 1]) * sscale[c + 1], 0.f);
                v.z = fmaxf((v.z - smean[c + 2]) * sscale[c + 2], 0.f);
                v.w = fmaxf((v.w - smean[c + 3]) * sscale[c + 3], 0.f);
                *(float4*)(h + (size_t)(row0 + r) * HID + c) = v;   // final h output
            }
            As[(k4 * 4 + 0) * 132 + r] = v.x;
            As[(k4 * 4 + 1) * 132 + r] = v.y;
            As[(k4 * 4 + 2) * 132 + r] = v.z;
            As[(k4 * 4 + 3) * 132 + r] = v.w;
        }
        #pragma unroll
        for (int i = 0; i < 4; i++) {
            int slot = tid + i * 256;
            int k  = slot >> 5;
            int c4 = slot & 31;
            *(float4*)(Bs + k * 128 + c4 * 4) =
                *(const float4*)(W + (size_t)(kc + k) * HID + c4 * 4);
        }
        __syncthreads();
        #pragma unroll
        for (int k = 0; k < 32; k++) {
            float4 a0 = *(float4*)(As + k * 132 + tr * 8);
            float4 a1 = *(float4*)(As + k * 132 + tr * 8 + 4);
            float4 b0 = *(float4*)(Bs + k * 128 + tc * 8);
            float4 b1 = *(float4*)(Bs + k * 128 + tc * 8 + 4);
            ull ap[4] = { pk2(a0.x, a0.y), pk2(a0.z, a0.w),
                          pk2(a1.x, a1.y), pk2(a1.z, a1.w) };
            ull bd[8] = { pk2(b0.x, b0.x), pk2(b0.y, b0.y),
                          pk2(b0.z, b0.z), pk2(b0.w, b0.w),
                          pk2(b1.x, b1.x), pk2(b1.y, b1.y),
                          pk2(b1.z, b1.z), pk2(b1.w, b1.w) };
            #pragma unroll
            for (int i = 0; i < 4; i++)
                #pragma unroll
                for (int j = 0; j < 8; j++)
                    fma2(acc[i][j], ap[i], bd[j]);
        }
        __syncthreads();
    }

    float w2[8], bb[8], wev[8];
    #pragma unroll
    for (int j = 0; j < 8; j++) {
        w2[j]  = l2w[tc * 8 + j];
        bb[j]  = g_base[tc * 8 + j];
        wev[j] = g_we[tc * 8 + j];
    }
    float b2 = l2b[0];
    #pragma unroll
    for (int i2 = 0; i2 < 4; i2++) {
        float2 v[8];
        #pragma unroll
        for (int j = 0; j < 8; j++) v[j] = upk2(acc[i2][j]);
        #pragma unroll
        for (int half = 0; half < 2; half++) {
            int row = row0 + tr * 8 + i2 * 2 + half;
            float e = (row < NODES) ? ecn[row] : 0.f;
            float s = 0.f;
            #pragma unroll
            for (int j = 0; j < 8; j++) {
                float val = half ? v[j].y : v[j].x;
                float t = val + bb[j] + e * wev[j];
                s += fmaxf(t, 0.f) * w2[j];
            }
            s += __shfl_xor_sync(0xffffffffu, s, 8, 16);
            s += __shfl_xor_sync(0xffffffffu, s, 4, 16);
            s += __shfl_xor_sync(0xffffffffu, s, 2, 16);
            s += __shfl_xor_sync(0xffffffffu, s, 1, 16);
            if (tc == 0) sarr[tr * 8 + i2 * 2 + half] = (row < NODES) ? (s + b2) : 0.f;
        }
    }
    if (tid < NPART) pp[tid] = 0.f;
    __syncthreads();
    int p = tid & 31, g = tid >> 5;
    float psum = 0.f;
    for (int r = g * 16; r < g * 16 + 16; r++) {
        int row = row0 + r;
        if (row < NODES) psum += sarr[r] * parts[(size_t)row * NPART + p];
    }
    atomicAdd(&pp[p], psum);
    __syncthreads();
    if (tid < NPART) atomicAdd(&out[tid], pp[tid]);
}

// ---------------- launcher ----------------
extern "C" void kernel_launch(void* const* d_in, const int* in_sizes, int n_in,
                              void* d_out, int out_size) {
    const float* x      = (const float*)d_in[0];
    const int*   ei     = (const int*)d_in[1];
    const float* ew     = (const float*)d_in[2];
    const float* parts  = (const float*)d_in[3];
    // d_in[4] = node_weights (unused by reference)
    const float* ecn    = (const float*)d_in[5];
    const float* conv_w = (const float*)d_in[6];
    const float* conv_b = (const float*)d_in[7];
    const float* l1w    = (const float*)d_in[8];
    const float* l1b    = (const float*)d_in[9];
    const float* l2w    = (const float*)d_in[10];
    const float* l2b    = (const float*)d_in[11];
    const int*   curr   = (const int*)d_in[12];

    float* out = (float*)d_out;          // [0:32) partition scores
    float* h   = out + NPART;            // [32 : 32+N*H) final h

    cudaStream_t sG;
    cudaStreamCreateWithFlags(&sG, cudaStreamNonBlocking);
    cudaEvent_t evFork, evJoin;
    cudaEventCreateWithFlags(&evFork, cudaEventDisableTiming);
    cudaEventCreateWithFlags(&evJoin, cudaEventDisableTiming);

    const int gemm_blocks = (NODES + 127) / 128;   // 391

    // fork sG off the (captured) default stream
    cudaEventRecord(evFork, 0);
    cudaStreamWaitEvent(sG, evFork, 0);

    // ---- setup chain on default stream ----
    zero_init_kernel<<<(NODES + 255) / 256, 256>>>(out);
    deg_count_kernel<<<(NE + 255) / 256, 256>>>(ei, ew);
    block_sum_kernel<<<NSB, SBLK>>>();
    // ---- gemm0 on sG, concurrent with setup (4th launch -> ncu target) ----
    gemm_kernel<<<gemm_blocks, 256, 0, sG>>>(x, conv_w, conv_b, -1, NODES);
    scan_bsum_kernel<<<1, 128>>>();
    scan_local_kernel<<<NSB, SBLK>>>();
    csr_fill_kernel<<<(NE + 255) / 256, 256>>>(ei, ew);

    // join: agg0 needs csr (default) + g_hw (sG) + zeroed stats (default)
    cudaEventRecord(evJoin, sG);
    cudaStreamWaitEvent(0, evJoin, 0);

    agg_kernel<<<1184, 256>>>(0);
    gemm_kernel<<<gemm_blocks, 256>>>(nullptr, conv_w + 1 * HID * HID,
                                      conv_b + 1 * HID, 0, NODES);
    agg_kernel<<<1184, 256>>>(1);
    gemm_kernel<<<gemm_blocks, 256>>>(nullptr, conv_w + 2 * HID * HID,
                                      conv_b + 2 * HID, 1, NODES);
    agg_kernel<<<1184, 256>>>(2);

    prep_kernel<<<1, 128>>>(l1w, l1b, curr);
    score_kernel<<<gemm_blocks, 256>>>(l1w, l2w, l2b, ecn, parts, h, out);
}

// round 8
// speedup vs baseline: 1.4855x; 1.0346x over previous
#include <cuda_runtime.h>

#define NODES 50000
#define NE    800000
#define HID   128
#define NPART 32
#define BN_EPS 1e-5f
#define SBLK  512
#define NSB   ((NODES + SBLK - 1) / SBLK)   // 98

typedef unsigned long long ull;

// ---------------- scratch (device globals; no runtime alloc) ----------------
__device__ float g_deg[NODES];
__device__ int   g_cnt[NODES];
__device__ int   g_off[NODES + 1];
__device__ int   g_cur[NODES];
__device__ float g_dinv[NODES];
__device__ int   g_bsum[NSB];
__device__ int   g_boff[NSB];
__device__ int2  g_csr[NE];                 // {src, float_as_int(norm)}
__device__ float g_hw[NODES * HID];
__device__ float g_agg[NODES * HID];
__device__ float g_stats[3 * 2 * HID];      // per layer: [0:128) sum, [128:256) sumsq
__device__ float g_base[HID];
__device__ float g_we[HID];

// ---------------- f32x2 helpers ----------------
__device__ __forceinline__ ull pk2(float lo, float hi) {
    ull r;
    asm("mov.b64 %0, {%1, %2};" : "=l"(r) : "f"(lo), "f"(hi));
    return r;
}
__device__ __forceinline__ void fma2(ull& d, ull a, ull b) {
    asm("fma.rn.f32x2 %0, %1, %2, %0;" : "+l"(d) : "l"(a), "l"(b));
}
__device__ __forceinline__ float2 upk2(ull v) {
    float2 f;
    asm("mov.b64 {%0, %1}, %2;" : "=f"(f.x), "=f"(f.y) : "l"(v));
    return f;
}
// ---------------- cp.async helpers ----------------
__device__ __forceinline__ void cpasync16(void* smem_ptr, const void* gptr) {
    unsigned s = (unsigned)__cvta_generic_to_shared(smem_ptr);
    asm volatile("cp.async.cg.shared.global [%0], [%1], 16;"
                 :: "r"(s), "l"(gptr) : "memory");
}
__device__ __forceinline__ void cpasync_commit() {
    asm volatile("cp.async.commit_group;" ::: "memory");
}
__device__ __forceinline__ void cpasync_wait_all() {
    asm volatile("cp.async.wait_group 0;" ::: "memory");
}

// ---------------- init ----------------
__global__ void zero_init_kernel(float* out) {
    int i = blockIdx.x * blockDim.x + threadIdx.x;
    if (i < NODES) { g_deg[i] = 0.f; g_cnt[i] = 0; g_cur[i] = 0; }
    if (i < NPART) out[i] = 0.f;
    if (i < 3 * 2 * HID) g_stats[i] = 0.f;
}

// ---------------- degree + count ----------------
__global__ void deg_count_kernel(const int* __restrict__ ei,
                                 const float* __restrict__ ew) {
    int e = blockIdx.x * blockDim.x + threadIdx.x;
    if (e >= NE) return;
    int dst = ei[NE + e];
    atomicAdd(&g_deg[dst], ew[e]);
    atomicAdd(&g_cnt[dst], 1);
}

// ---------------- scan stage 1: per-block sums (+ dinv fused) ----------------
__global__ __launch_bounds__(SBLK) void block_sum_kernel() {
    __shared__ int ws[SBLK / 32];
    int t = threadIdx.x, lane = t & 31, w = t >> 5;
    int i = blockIdx.x * SBLK + t;
    int v = (i < NODES) ? g_cnt[i] : 0;
    if (i < NODES) g_dinv[i] = rsqrtf(g_deg[i] + 1.0f);
    int s = v;
    #pragma unroll
    for (int o = 16; o; o >>= 1) s += __shfl_down_sync(0xffffffffu, s, o);
    if (lane == 0) ws[w] = s;
    __syncthreads();
    if (t < SBLK / 32) {
        int x = ws[t];
        #pragma unroll
        for (int o = 8; o; o >>= 1) x += __shfl_down_sync(0x0000ffffu, x, o);
        if (t == 0) g_bsum[blockIdx.x] = x;
    }
}

// ---------------- scan stage 2 ----------------
__global__ void scan_bsum_kernel() {
    __shared__ int ws[4];
    int t = threadIdx.x, lane = t & 31, w = t >> 5;
    int v = (t < NSB) ? g_bsum[t] : 0;
    int inc = v;
    #pragma unroll
    for (int o = 1; o < 32; o <<= 1) {
        int u = __shfl_up_sync(0xffffffffu, inc, o);
        if (lane >= o) inc += u;
    }
    if (lane == 31) ws[w] = inc;
    __syncthreads();
    int add = 0;
    for (int k = 0; k < w; k++) add += ws[k];
    if (t < NSB) g_boff[t] = add + inc - v;
    if (t == NSB - 1) g_off[NODES] = add + inc;
}

// ---------------- scan stage 3 ----------------
__global__ __launch_bounds__(SBLK) void scan_local_kernel() {
    __shared__ int ws[SBLK / 32];
    int t = threadIdx.x, lane = t & 31, w = t >> 5;
    int i = blockIdx.x * SBLK + t;
    int v = (i < NODES) ? g_cnt[i] : 0;
    int inc = v;
    #pragma unroll
    for (int o = 1; o < 32; o <<= 1) {
        int u = __shfl_up_sync(0xffffffffu, inc, o);
        if (lane >= o) inc += u;
    }
    if (lane == 31) ws[w] = inc;
    __syncthreads();
    int add = g_boff[blockIdx.x];
    for (int k = 0; k < w; k++) add += ws[k];
    if (i < NODES) g_off[i] = add + inc - v;
}

// ---------------- CSR fill (interleaved) ----------------
__global__ void csr_fill_kernel(const int* __restrict__ ei,
                                const float* __restrict__ ew) {
    int e = blockIdx.x * blockDim.x + threadIdx.x;
    if (e >= NE) return;
    int src = ei[e];
    int dst = ei[NE + e];
    int pos = g_off[dst] + atomicAdd(&g_cur[dst], 1);
    float norm = g_dinv[src] * ew[e] * g_dinv[dst];
    g_csr[pos] = make_int2(src, __float_as_int(norm));
}

// ==================== pipelined GEMM: g_hw = act(A)[nrows,128] @ W + bias ====================
// UNCHANGED from R7 (regs=123, right at the 2-block cliff — do not touch).
#define KC 16
#define NCHUNK (HID / KC)   // 8
__global__ __launch_bounds__(256) void gemm_kernel(
    const float* __restrict__ A, const float* __restrict__ W,
    const float* __restrict__ bias, int layer, int nrows)
{
    __shared__ float As[2][KC * 132];   // [k][row], padded
    __shared__ float Bs[2][KC * 128];   // [k][col]
    __shared__ float smean[HID], sscale[HID];
    const bool bn = (layer >= 0);
    const float* __restrict__ src = bn ? (const float*)g_agg : A;
    int tid = threadIdx.x;
    int tr = tid >> 4, tc = tid & 15;
    int row0 = blockIdx.x * 128;

    if (bn && tid < HID) {
        float m = g_stats[layer * 256 + tid] * (1.0f / NODES);
        float v = g_stats[layer * 256 + HID + tid] * (1.0f / NODES) - m * m;
        smean[tid]  = m;
        sscale[tid] = rsqrtf(v + BN_EPS);
    }

    int rA[2], k4A[2];
    bool okA[2];
    #pragma unroll
    for (int i = 0; i < 2; i++) {
        int slot = tid + i * 256;
        rA[i]  = slot >> 2;
        k4A[i] = slot & 3;
        okA[i] = (row0 + rA[i]) < nrows;
    }
    int kB[2], c4B[2];
    #pragma unroll
    for (int i = 0; i < 2; i++) {
        int slot = tid + i * 256;
        kB[i]  = slot >> 5;
        c4B[i] = slot & 31;
    }

    ull acc[4][8];
    #pragma unroll
    for (int i = 0; i < 4; i++)
        #pragma unroll
        for (int j = 0; j < 8; j++) acc[i][j] = 0ull;

    float4 pa[2];
    #pragma unroll
    for (int i = 0; i < 2; i++)
        pa[i] = okA[i]
              ? *(const float4*)(src + (size_t)(row0 + rA[i]) * HID + k4A[i] * 4)
              : make_float4(0.f, 0.f, 0.f, 0.f);
    #pragma unroll
    for (int i = 0; i < 2; i++)
        cpasync16(&Bs[0][kB[i] * 128 + c4B[i] * 4],
                  W + (size_t)kB[i] * HID + c4B[i] * 4);
    cpasync_commit();
    __syncthreads();
    #pragma unroll
    for (int i = 0; i < 2; i++) {
        float v4[4] = { pa[i].x, pa[i].y, pa[i].z, pa[i].w };
        #pragma unroll
        for (int j = 0; j < 4; j++) {
            float v = v4[j];
            if (bn) {
                int col = k4A[i] * 4 + j;
                v = fmaxf((v - smean[col]) * sscale[col], 0.f);
            }
            As[0][(k4A[i] * 4 + j) * 132 + rA[i]] = v;
        }
    }
    #pragma unroll
    for (int i = 0; i < 2; i++)
        pa[i] = okA[i]
              ? *(const float4*)(src + (size_t)(row0 + rA[i]) * HID + KC + k4A[i] * 4)
              : make_float4(0.f, 0.f, 0.f, 0.f);

    #pragma unroll 1
    for (int c = 0; c < NCHUNK; c++) {
        cpasync_wait_all();
        __syncthreads();
        int nb = (c + 1) & 1;
        if (c + 1 < NCHUNK) {
            #pragma unroll
            for (int i = 0; i < 2; i++)
                cpasync16(&Bs[nb][kB[i] * 128 + c4B[i] * 4],
                          W + (size_t)((c + 1) * KC + kB[i]) * HID + c4B[i] * 4);
            cpasync_commit();
            #pragma unroll
            for (int i = 0; i < 2; i++) {
                float v4[4] = { pa[i].x, pa[i].y, pa[i].z, pa[i].w };
                #pragma unroll
                for (int j = 0; j < 4; j++) {
                    float v = v4[j];
                    if (bn) {
                        int col = (c + 1) * KC + k4A[i] * 4 + j;
                        v = fmaxf((v - smean[col]) * sscale[col], 0.f);
                    }
                    As[nb][(k4A[i] * 4 + j) * 132 + rA[i]] = v;
                }
            }
        }
        if (c + 2 < NCHUNK) {
            #pragma unroll
            for (int i = 0; i < 2; i++)
                pa[i] = okA[i]
                      ? *(const float4*)(src + (size_t)(row0 + rA[i]) * HID
                                         + (c + 2) * KC + k4A[i] * 4)
                      : make_float4(0.f, 0.f, 0.f, 0.f);
        }
        const float* as = As[c & 1];
        const float* bs = Bs[c & 1];
        #pragma unroll
        for (int k = 0; k < KC; k++) {
            float4 a0 = *(const float4*)(as + k * 132 + tr * 8);
            float4 a1 = *(const float4*)(as + k * 132 + tr * 8 + 4);
            float4 b0 = *(const float4*)(bs + k * 128 + tc * 8);
            float4 b1 = *(const float4*)(bs + k * 128 + tc * 8 + 4);
            ull ap[4] = { pk2(a0.x, a0.y), pk2(a0.z, a0.w),
                          pk2(a1.x, a1.y), pk2(a1.z, a1.w) };
            ull bd[8] = { pk2(b0.x, b0.x), pk2(b0.y, b0.y),
                          pk2(b0.z, b0.z), pk2(b0.w, b0.w),
                          pk2(b1.x, b1.x), pk2(b1.y, b1.y),
                          pk2(b1.z, b1.z), pk2(b1.w, b1.w) };
            #pragma unroll
            for (int i = 0; i < 4; i++)
                #pragma unroll
                for (int j = 0; j < 8; j++)
                    fma2(acc[i][j], ap[i], bd[j]);
        }
    }

    float bv[8];
    #pragma unroll
    for (int j = 0; j < 8; j++) bv[j] = bias[tc * 8 + j];
    #pragma unroll
    for (int i2 = 0; i2 < 4; i2++) {
        float2 v[8];
        #pragma unroll
        for (int j = 0; j < 8; j++) v[j] = upk2(acc[i2][j]);
        int r0 = row0 + tr * 8 + i2 * 2;
        if (r0 < nrows) {
            float4 o0 = make_float4(v[0].x + bv[0], v[1].x + bv[1],
                                    v[2].x + bv[2], v[3].x + bv[3]);
            float4 o1 = make_float4(v[4].x + bv[4], v[5].x + bv[5],
                                    v[6].x + bv[6], v[7].x + bv[7]);
            *(float4*)(g_hw + (size_t)r0 * HID + tc * 8)     = o0;
            *(float4*)(g_hw + (size_t)r0 * HID + tc * 8 + 4) = o1;
        }
        if (r0 + 1 < nrows) {
            float4 o0 = make_float4(v[0].y + bv[0], v[1].y + bv[1],
                                    v[2].y + bv[2], v[3].y + bv[3]);
            float4 o1 = make_float4(v[4].y + bv[4], v[5].y + bv[5],
                                    v[6].y + bv[6], v[7].y + bv[7]);
            *(float4*)(g_hw + (size_t)(r0 + 1) * HID + tc * 8)     = o0;
            *(float4*)(g_hw + (size_t)(r0 + 1) * HID + tc * 8 + 4) = o1;
        }
    }
}

// ---------------- aggregation (warp per node, gather unrolled x4) + BN stats ----------------
__global__ __launch_bounds__(256) void agg_kernel(int layer) {
    __shared__ float bsum[HID];
    __shared__ float bss[HID];
    int tid = threadIdx.x;
    for (int i = tid; i < HID; i += blockDim.x) { bsum[i] = 0.f; bss[i] = 0.f; }
    __syncthreads();

    int lane = tid & 31;
    int wglobal = (blockIdx.x * blockDim.x + tid) >> 5;
    int nwarps  = (gridDim.x * blockDim.x) >> 5;

    float ls0 = 0.f, ls1 = 0.f, ls2 = 0.f, ls3 = 0.f;
    float lq0 = 0.f, lq1 = 0.f, lq2 = 0.f, lq3 = 0.f;

    for (int n = wglobal; n < NODES; n += nwarps) {
        float dv = g_dinv[n];
        float sn = dv * dv;
        float4 a = ((const float4*)(g_hw + (size_t)n * HID))[lane];
        float4 acc = make_float4(a.x * sn, a.y * sn, a.z * sn, a.w * sn);
        int beg = g_off[n], end = g_off[n + 1];
        int i = beg;
        for (; i + 4 <= end; i += 4) {
            int2 e0 = g_csr[i],     e1 = g_csr[i + 1];
            int2 e2 = g_csr[i + 2], e3 = g_csr[i + 3];
            float w0 = __int_as_float(e0.y), w1 = __int_as_float(e1.y);
            float w2 = __int_as_float(e2.y), w3 = __int_as_float(e3.y);
            float4 v0 = ((const float4*)(g_hw + (size_t)e0.x * HID))[lane];
            float4 v1 = ((const float4*)(g_hw + (size_t)e1.x * HID))[lane];
            float4 v2 = ((const float4*)(g_hw + (size_t)e2.x * HID))[lane];
            float4 v3 = ((const float4*)(g_hw + (size_t)e3.x * HID))[lane];
            acc.x += w0 * v0.x + w1 * v1.x + w2 * v2.x + w3 * v3.x;
            acc.y += w0 * v0.y + w1 * v1.y + w2 * v2.y + w3 * v3.y;
            acc.z += w0 * v0.z + w1 * v1.z + w2 * v2.z + w3 * v3.z;
            acc.w += w0 * v0.w + w1 * v1.w + w2 * v2.w + w3 * v3.w;
        }
        for (; i + 2 <= end; i += 2) {
            int2 e0 = g_csr[i], e1 = g_csr[i + 1];
            float w0 = __int_as_float(e0.y), w1 = __int_as_float(e1.y);
            float4 v0 = ((const float4*)(g_hw + (size_t)e0.x * HID))[lane];
            float4 v1 = ((const float4*)(g_hw + (size_t)e1.x * HID))[lane];
            acc.x += w0 * v0.x + w1 * v1.x;
            acc.y += w0 * v0.y + w1 * v1.y;
            acc.z += w0 * v0.z + w1 * v1.z;
            acc.w += w0 * v0.w + w1 * v1.w;
        }
        if (i < end) {
            int2 e0 = g_csr[i];
            float w = __int_as_float(e0.y);
            float4 v = ((const float4*)(g_hw + (size_t)e0.x * HID))[lane];
            acc.x += w * v.x; acc.y += w * v.y;
            acc.z += w * v.z; acc.w += w * v.w;
        }
        ((float4*)(g_agg + (size_t)n * HID))[lane] = acc;
        ls0 += acc.x; ls1 += acc.y; ls2 += acc.z; ls3 += acc.w;
        lq0 += acc.x * acc.x; lq1 += acc.y * acc.y;
        lq2 += acc.z * acc.z; lq3 += acc.w * acc.w;
    }
    int c = lane * 4;
    atomicAdd(&bsum[c + 0], ls0); atomicAdd(&bsum[c + 1], ls1);
    atomicAdd(&bsum[c + 2], ls2); atomicAdd(&bsum[c + 3], ls3);
    atomicAdd(&bss[c + 0], lq0);  atomicAdd(&bss[c + 1], lq1);
    atomicAdd(&bss[c + 2], lq2);  atomicAdd(&bss[c + 3], lq3);
    __syncthreads();
    for (int i = tid; i < HID; i += blockDim.x) {
        atomicAdd(&g_stats[layer * 256 + i],       bsum[i]);
        atomicAdd(&g_stats[layer * 256 + HID + i], bss[i]);
    }
}

// ---------------- scoring prep (reads g_agg + stats[2] directly) ----------------
__global__ void prep_kernel(const float* __restrict__ l1w,
                            const float* __restrict__ l1b,
                            const int* __restrict__ curr) {
    __shared__ float xs[HID];
    int j = threadIdx.x;   // 128
    int c = *curr;
    float m = g_stats[2 * 256 + j] * (1.0f / NODES);
    float v = g_stats[2 * 256 + HID + j] * (1.0f / NODES) - m * m;
    float sc = rsqrtf(v + BN_EPS);
    xs[j] = fmaxf((g_agg[(size_t)c * HID + j] - m) * sc, 0.f);
    __syncthreads();
    float acc = 0.f;
    #pragma unroll 8
    for (int k = 0; k < HID; k++)
        acc += xs[k] * l1w[(size_t)(HID + k) * HID + j];
    g_base[j] = l1b[j] + acc;
    float we = 0.f;
    #pragma unroll 8
    for (int k = 2 * HID; k < 4 * HID; k++)
        we += l1w[(size_t)k * HID + j];
    g_we[j] = we;
}

// ==================== pipelined scoring: BN+ReLU on A-load (writes h) + GEMM + pooling ====================
__global__ __launch_bounds__(256, 2) void score_kernel(
    const float* __restrict__ W,    // lin1_w rows 0..127
    const float* __restrict__ l2w, const float* __restrict__ l2b,
    const float* __restrict__ ecn, const float* __restrict__ parts,
    float* __restrict__ h, float* __restrict__ out)
{
    __shared__ float As[2][KC * 132];
    __shared__ float Bs[2][KC * 128];
    __shared__ float smean[HID], sscale[HID];
    __shared__ float sarr[128];
    __shared__ float pp[NPART];
    int tid = threadIdx.x;
    int tr = tid >> 4, tc = tid & 15;
    int row0 = blockIdx.x * 128;

    if (tid < HID) {
        float m = g_stats[2 * 256 + tid] * (1.0f / NODES);
        float v = g_stats[2 * 256 + HID + tid] * (1.0f / NODES) - m * m;
        smean[tid]  = m;
        sscale[tid] = rsqrtf(v + BN_EPS);
    }

    int rA[2], k4A[2];
    bool okA[2];
    #pragma unroll
    for (int i = 0; i < 2; i++) {
        int slot = tid + i * 256;
        rA[i]  = slot >> 2;
        k4A[i] = slot & 3;
        okA[i] = (row0 + rA[i]) < NODES;
    }
    int kB[2], c4B[2];
    #pragma unroll
    for (int i = 0; i < 2; i++) {
        int slot = tid + i * 256;
        kB[i]  = slot >> 5;
        c4B[i] = slot & 31;
    }

    ull acc[4][8];
    #pragma unroll
    for (int i = 0; i < 4; i++)
        #pragma unroll
        for (int j = 0; j < 8; j++) acc[i][j] = 0ull;

    float4 pa[2];
    #pragma unroll
    for (int i = 0; i < 2; i++)
        pa[i] = okA[i]
              ? *(const float4*)(g_agg + (size_t)(row0 + rA[i]) * HID + k4A[i] * 4)
              : make_float4(0.f, 0.f, 0.f, 0.f);
    #pragma unroll
    for (int i = 0; i < 2; i++)
        cpasync16(&Bs[0][kB[i] * 128 + c4B[i] * 4],
                  W + (size_t)kB[i] * HID + c4B[i] * 4);
    cpasync_commit();
    __syncthreads();   // smean/sscale ready
    // STS chunk 0: BN+ReLU, write h, stage to As
    #pragma unroll
    for (int i = 0; i < 2; i++) {
        float v4[4] = { pa[i].x, pa[i].y, pa[i].z, pa[i].w };
        float o4[4];
        #pragma unroll
        for (int j = 0; j < 4; j++) {
            int col = k4A[i] * 4 + j;
            o4[j] = fmaxf((v4[j] - smean[col]) * sscale[col], 0.f);
            As[0][col * 132 + rA[i]] = o4[j];
        }
        if (okA[i])
            *(float4*)(h + (size_t)(row0 + rA[i]) * HID + k4A[i] * 4) =
                make_float4(o4[0], o4[1], o4[2], o4[3]);
    }
    #pragma unroll
    for (int i = 0; i < 2; i++)
        pa[i] = okA[i]
              ? *(const float4*)(g_agg + (size_t)(row0 + rA[i]) * HID + KC + k4A[i] * 4)
              : make_float4(0.f, 0.f, 0.f, 0.f);

    #pragma unroll 1
    for (int c = 0; c < NCHUNK; c++) {
        cpasync_wait_all();
        __syncthreads();
        int nb = (c + 1) & 1;
        if (c + 1 < NCHUNK) {
            #pragma unroll
            for (int i = 0; i < 2; i++)
                cpasync16(&Bs[nb][kB[i] * 128 + c4B[i] * 4],
                          W + (size_t)((c + 1) * KC + kB[i]) * HID + c4B[i] * 4);
            cpasync_commit();
            #pragma unroll
            for (int i = 0; i < 2; i++) {
                float v4[4] = { pa[i].x, pa[i].y, pa[i].z, pa[i].w };
                float o4[4];
                #pragma unroll
                for (int j = 0; j < 4; j++) {
                    int col = (c + 1) * KC + k4A[i] * 4 + j;
                    o4[j] = fmaxf((v4[j] - smean[col]) * sscale[col], 0.f);
                    As[nb][(k4A[i] * 4 + j) * 132 + rA[i]] = o4[j];
                }
                if (okA[i])
                    *(float4*)(h + (size_t)(row0 + rA[i]) * HID
                               + (c + 1) * KC + k4A[i] * 4) =
                        make_float4(o4[0], o4[1], o4[2], o4[3]);
            }
        }
        if (c + 2 < NCHUNK) {
            #pragma unroll
            for (int i = 0; i < 2; i++)
                pa[i] = okA[i]
                      ? *(const float4*)(g_agg + (size_t)(row0 + rA[i]) * HID
                                         + (c + 2) * KC + k4A[i] * 4)
                      : make_float4(0.f, 0.f, 0.f, 0.f);
        }
        const float* as = As[c & 1];
        const float* bs = Bs[c & 1];
        #pragma unroll
        for (int k = 0; k < KC; k++) {
            float4 a0 = *(const float4*)(as + k * 132 + tr * 8);
            float4 a1 = *(const float4*)(as + k * 132 + tr * 8 + 4);
            float4 b0 = *(const float4*)(bs + k * 128 + tc * 8);
            float4 b1 = *(const float4*)(bs + k * 128 + tc * 8 + 4);
            ull ap[4] = { pk2(a0.x, a0.y), pk2(a0.z, a0.w),
                          pk2(a1.x, a1.y), pk2(a1.z, a1.w) };
            ull bd[8] = { pk2(b0.x, b0.x), pk2(b0.y, b0.y),
                          pk2(b0.z, b0.z), pk2(b0.w, b0.w),
                          pk2(b1.x, b1.x), pk2(b1.y, b1.y),
                          pk2(b1.z, b1.z), pk2(b1.w, b1.w) };
            #pragma unroll
            for (int i = 0; i < 4; i++)
                #pragma unroll
                for (int j = 0; j < 8; j++)
                    fma2(acc[i][j], ap[i], bd[j]);
        }
    }

    float w2[8], bb[8], wev[8];
    #pragma unroll
    for (int j = 0; j < 8; j++) {
        w2[j]  = l2w[tc * 8 + j];
        bb[j]  = g_base[tc * 8 + j];
        wev[j] = g_we[tc * 8 + j];
    }
    float b2 = l2b[0];
    #pragma unroll
    for (int i2 = 0; i2 < 4; i2++) {
        float2 v[8];
        #pragma unroll
        for (int j = 0; j < 8; j++) v[j] = upk2(acc[i2][j]);
        #pragma unroll
        for (int half = 0; half < 2; half++) {
            int row = row0 + tr * 8 + i2 * 2 + half;
            float e = (row < NODES) ? ecn[row] : 0.f;
            float s = 0.f;
            #pragma unroll
            for (int j = 0; j < 8; j++) {
                float val = half ? v[j].y : v[j].x;
                float t = val + bb[j] + e * wev[j];
                s += fmaxf(t, 0.f) * w2[j];
            }
            s += __shfl_xor_sync(0xffffffffu, s, 8, 16);
            s += __shfl_xor_sync(0xffffffffu, s, 4, 16);
            s += __shfl_xor_sync(0xffffffffu, s, 2, 16);
            s += __shfl_xor_sync(0xffffffffu, s, 1, 16);
            if (tc == 0) sarr[tr * 8 + i2 * 2 + half] = (row < NODES) ? (s + b2) : 0.f;
        }
    }
    if (tid < NPART) pp[tid] = 0.f;
    __syncthreads();
    int p = tid & 31, g = tid >> 5;
    float psum = 0.f;
    for (int r = g * 16; r < g * 16 + 16; r++) {
        int row = row0 + r;
        if (row < NODES) psum += sarr[r] * parts[(size_t)row * NPART + p];
    }
    atomicAdd(&pp[p], psum);
    __syncthreads();
    if (tid < NPART) atomicAdd(&out[tid], pp[tid]);
}

// ---------------- launcher ----------------
extern "C" void kernel_launch(void* const* d_in, const int* in_sizes, int n_in,
                              void* d_out, int out_size) {
    const float* x      = (const float*)d_in[0];
    const int*   ei     = (const int*)d_in[1];
    const float* ew     = (const float*)d_in[2];
    const float* parts  = (const float*)d_in[3];
    // d_in[4] = node_weights (unused by reference)
    const float* ecn    = (const float*)d_in[5];
    const float* conv_w = (const float*)d_in[6];
    const float* conv_b = (const float*)d_in[7];
    const float* l1w    = (const float*)d_in[8];
    const float* l1b    = (const float*)d_in[9];
    const float* l2w    = (const float*)d_in[10];
    const float* l2b    = (const float*)d_in[11];
    const int*   curr   = (const int*)d_in[12];

    float* out = (float*)d_out;          // [0:32) partition scores
    float* h   = out + NPART;            // [32 : 32+N*H) final h

    cudaStream_t sG;
    cudaStreamCreateWithFlags(&sG, cudaStreamNonBlocking);
    cudaEvent_t evFork, evJoin;
    cudaEventCreateWithFlags(&evFork, cudaEventDisableTiming);
    cudaEventCreateWithFlags(&evJoin, cudaEventDisableTiming);

    const int gemm_blocks = (NODES + 127) / 128;   // 391

    // fork sG off the (captured) default stream
    cudaEventRecord(evFork, 0);
    cudaStreamWaitEvent(sG, evFork, 0);

    // ---- setup chain on default stream ----
    zero_init_kernel<<<(NODES + 255) / 256, 256>>>(out);
    deg_count_kernel<<<(NE + 255) / 256, 256>>>(ei, ew);
    block_sum_kernel<<<NSB, SBLK>>>();
    // ---- gemm0 on sG, concurrent with setup (4th launch -> ncu target) ----
    gemm_kernel<<<gemm_blocks, 256, 0, sG>>>(x, conv_w, conv_b, -1, NODES);
    scan_bsum_kernel<<<1, 128>>>();
    scan_local_kernel<<<NSB, SBLK>>>();
    csr_fill_kernel<<<(NE + 255) / 256, 256>>>(ei, ew);

    // join: agg0 needs csr (default) + g_hw (sG) + zeroed stats (default)
    cudaEventRecord(evJoin, sG);
    cudaStreamWaitEvent(0, evJoin, 0);

    agg_kernel<<<1184, 256>>>(0);
    gemm_kernel<<<gemm_blocks, 256>>>(nullptr, conv_w + 1 * HID * HID,
                                      conv_b + 1 * HID, 0, NODES);
    agg_kernel<<<1184, 256>>>(1);
    gemm_kernel<<<gemm_blocks, 256>>>(nullptr, conv_w + 2 * HID * HID,
                                      conv_b + 2 * HID, 1, NODES);
    agg_kernel<<<1184, 256>>>(2);

    prep_kernel<<<1, 128>>>(l1w, l1b, curr);
    score_kernel<<<gemm_blocks, 256>>>(l1w, l2w, l2b, ecn, parts, h, out);
}

// round 9
// speedup vs baseline: 1.4921x; 1.0044x over previous
#include <cuda_runtime.h>

#define NODES 50000
#define NE    800000
#define HID   128
#define NPART 32
#define BN_EPS 1e-5f
#define SBLK  512
#define NSB   ((NODES + SBLK - 1) / SBLK)   // 98

typedef unsigned long long ull;

// ---------------- scratch (device globals; no runtime alloc) ----------------
__device__ float g_deg[NODES];
__device__ int   g_cnt[NODES];
__device__ int   g_off[NODES + 1];
__device__ int   g_cur[NODES];
__device__ float g_dinv[NODES];
__device__ int   g_aggv[NSB];
__device__ volatile int g_flag[NSB];
__device__ int2  g_csr[NE];                 // {src, float_as_int(norm)}
__device__ float g_hw[NODES * HID];
__device__ float g_agg[NODES * HID];
__device__ float g_stats[3 * 2 * HID];      // per layer: [0:128) sum, [128:256) sumsq
__device__ float g_base[HID];
__device__ float g_we[HID];

// ---------------- f32x2 helpers ----------------
__device__ __forceinline__ ull pk2(float lo, float hi) {
    ull r;
    asm("mov.b64 %0, {%1, %2};" : "=l"(r) : "f"(lo), "f"(hi));
    return r;
}
__device__ __forceinline__ void fma2(ull& d, ull a, ull b) {
    asm("fma.rn.f32x2 %0, %1, %2, %0;" : "+l"(d) : "l"(a), "l"(b));
}
__device__ __forceinline__ float2 upk2(ull v) {
    float2 f;
    asm("mov.b64 {%0, %1}, %2;" : "=f"(f.x), "=f"(f.y) : "l"(v));
    return f;
}
// ---------------- cp.async helpers ----------------
__device__ __forceinline__ void cpasync16(void* smem_ptr, const void* gptr) {
    unsigned s = (unsigned)__cvta_generic_to_shared(smem_ptr);
    asm volatile("cp.async.cg.shared.global [%0], [%1], 16;"
                 :: "r"(s), "l"(gptr) : "memory");
}
__device__ __forceinline__ void cpasync_commit() {
    asm volatile("cp.async.commit_group;" ::: "memory");
}
__device__ __forceinline__ void cpasync_wait_all() {
    asm volatile("cp.async.wait_group 0;" ::: "memory");
}

// ---------------- init ----------------
__global__ void zero_init_kernel(float* out) {
    int i = blockIdx.x * blockDim.x + threadIdx.x;
    if (i < NODES) { g_deg[i] = 0.f; g_cnt[i] = 0; g_cur[i] = 0; }
    if (i < NPART) out[i] = 0.f;
    if (i < 3 * 2 * HID) g_stats[i] = 0.f;
    if (i < NSB) g_flag[i] = 0;
}

// ---------------- degree + count ----------------
__global__ void deg_count_kernel(const int* __restrict__ ei,
                                 const float* __restrict__ ew) {
    int e = blockIdx.x * blockDim.x + threadIdx.x;
    if (e >= NE) return;
    int dst = ei[NE + e];
    atomicAdd(&g_deg[dst], ew[e]);
    atomicAdd(&g_cnt[dst], 1);
}

// ---------------- single-kernel scan (decoupled lookback) + dinv fused ----------------
__global__ __launch_bounds__(SBLK) void scan_kernel2() {
    __shared__ int ws[SBLK / 32];
    __shared__ int s_prefix;
    int t = threadIdx.x, lane = t & 31, w = t >> 5;
    int bid = blockIdx.x;
    int i = bid * SBLK + t;
    int v = (i < NODES) ? g_cnt[i] : 0;
    if (i < NODES) g_dinv[i] = rsqrtf(g_deg[i] + 1.0f);

    // inclusive warp scan
    int inc = v;
    #pragma unroll
    for (int o = 1; o < 32; o <<= 1) {
        int u = __shfl_up_sync(0xffffffffu, inc, o);
        if (lane >= o) inc += u;
    }
    if (lane == 31) ws[w] = inc;
    __syncthreads();

    // warp 0: scan the 16 warp sums; publish block total ASAP
    if (w == 0 && lane < SBLK / 32) {
        int x = ws[lane];
        int xi = x;
        #pragma unroll
        for (int o = 1; o < 16; o <<= 1) {
            int u = __shfl_up_sync(0x0000ffffu, xi, o);
            if (lane >= o) xi += u;
        }
        ws[lane] = xi - x;                 // exclusive warp offsets
        if (lane == SBLK / 32 - 1) {       // xi = block total
            g_aggv[bid] = xi;
            __threadfence();
            g_flag[bid] = 1;
        }
    }
    __syncthreads();

    // warp 0: lookback — sum ALL predecessor aggregates (windowed, lane-parallel)
    if (w == 0) {
        int sum = 0;
        for (int base = 0; base < bid; base += 32) {
            int p = base + lane;
            int a = 0;
            if (p < bid) {
                while (g_flag[p] == 0) { }
                __threadfence();
                a = g_aggv[p];
            }
            #pragma unroll
            for (int o = 16; o; o >>= 1) a += __shfl_down_sync(0xffffffffu, a, o);
            if (lane == 0) sum += a;
        }
        if (lane == 0) s_prefix = sum;
    }
    __syncthreads();

    int pref = s_prefix;
    if (i < NODES) g_off[i] = pref + ws[w] + inc - v;
    if (bid == NSB - 1 && t == SBLK - 1) g_off[NODES] = pref + ws[w] + inc;
}

// ---------------- CSR fill (interleaved) ----------------
__global__ void csr_fill_kernel(const int* __restrict__ ei,
                                const float* __restrict__ ew) {
    int e = blockIdx.x * blockDim.x + threadIdx.x;
    if (e >= NE) return;
    int src = ei[e];
    int dst = ei[NE + e];
    int pos = g_off[dst] + atomicAdd(&g_cur[dst], 1);
    float norm = g_dinv[src] * ew[e] * g_dinv[dst];
    g_csr[pos] = make_int2(src, __float_as_int(norm));
}

// ==================== pipelined GEMM (frozen since R7; regs=123 at 2-block cliff) ====================
#define KC 16
#define NCHUNK (HID / KC)   // 8
__global__ __launch_bounds__(256) void gemm_kernel(
    const float* __restrict__ A, const float* __restrict__ W,
    const float* __restrict__ bias, int layer, int nrows)
{
    __shared__ float As[2][KC * 132];   // [k][row], padded
    __shared__ float Bs[2][KC * 128];   // [k][col]
    __shared__ float smean[HID], sscale[HID];
    const bool bn = (layer >= 0);
    const float* __restrict__ src = bn ? (const float*)g_agg : A;
    int tid = threadIdx.x;
    int tr = tid >> 4, tc = tid & 15;
    int row0 = blockIdx.x * 128;

    if (bn && tid < HID) {
        float m = g_stats[layer * 256 + tid] * (1.0f / NODES);
        float v = g_stats[layer * 256 + HID + tid] * (1.0f / NODES) - m * m;
        smean[tid]  = m;
        sscale[tid] = rsqrtf(v + BN_EPS);
    }

    int rA[2], k4A[2];
    bool okA[2];
    #pragma unroll
    for (int i = 0; i < 2; i++) {
        int slot = tid + i * 256;
        rA[i]  = slot >> 2;
        k4A[i] = slot & 3;
        okA[i] = (row0 + rA[i]) < nrows;
    }
    int kB[2], c4B[2];
    #pragma unroll
    for (int i = 0; i < 2; i++) {
        int slot = tid + i * 256;
        kB[i]  = slot >> 5;
        c4B[i] = slot & 31;
    }

    ull acc[4][8];
    #pragma unroll
    for (int i = 0; i < 4; i++)
        #pragma unroll
        for (int j = 0; j < 8; j++) acc[i][j] = 0ull;

    float4 pa[2];
    #pragma unroll
    for (int i = 0; i < 2; i++)
        pa[i] = okA[i]
              ? *(const float4*)(src + (size_t)(row0 + rA[i]) * HID + k4A[i] * 4)
              : make_float4(0.f, 0.f, 0.f, 0.f);
    #pragma unroll
    for (int i = 0; i < 2; i++)
        cpasync16(&Bs[0][kB[i] * 128 + c4B[i] * 4],
                  W + (size_t)kB[i] * HID + c4B[i] * 4);
    cpasync_commit();
    __syncthreads();
    #pragma unroll
    for (int i = 0; i < 2; i++) {
        float v4[4] = { pa[i].x, pa[i].y, pa[i].z, pa[i].w };
        #pragma unroll
        for (int j = 0; j < 4; j++) {
            float v = v4[j];
            if (bn) {
                int col = k4A[i] * 4 + j;
                v = fmaxf((v - smean[col]) * sscale[col], 0.f);
            }
            As[0][(k4A[i] * 4 + j) * 132 + rA[i]] = v;
        }
    }
    #pragma unroll
    for (int i = 0; i < 2; i++)
        pa[i] = okA[i]
              ? *(const float4*)(src + (size_t)(row0 + rA[i]) * HID + KC + k4A[i] * 4)
              : make_float4(0.f, 0.f, 0.f, 0.f);

    #pragma unroll 1
    for (int c = 0; c < NCHUNK; c++) {
        cpasync_wait_all();
        __syncthreads();
        int nb = (c + 1) & 1;
        if (c + 1 < NCHUNK) {
            #pragma unroll
            for (int i = 0; i < 2; i++)
                cpasync16(&Bs[nb][kB[i] * 128 + c4B[i] * 4],
                          W + (size_t)((c + 1) * KC + kB[i]) * HID + c4B[i] * 4);
            cpasync_commit();
            #pragma unroll
            for (int i = 0; i < 2; i++) {
                float v4[4] = { pa[i].x, pa[i].y, pa[i].z, pa[i].w };
                #pragma unroll
                for (int j = 0; j < 4; j++) {
                    float v = v4[j];
                    if (bn) {
                        int col = (c + 1) * KC + k4A[i] * 4 + j;
                        v = fmaxf((v - smean[col]) * sscale[col], 0.f);
                    }
                    As[nb][(k4A[i] * 4 + j) * 132 + rA[i]] = v;
                }
            }
        }
        if (c + 2 < NCHUNK) {
            #pragma unroll
            for (int i = 0; i < 2; i++)
                pa[i] = okA[i]
                      ? *(const float4*)(src + (size_t)(row0 + rA[i]) * HID
                                         + (c + 2) * KC + k4A[i] * 4)
                      : make_float4(0.f, 0.f, 0.f, 0.f);
        }
        const float* as = As[c & 1];
        const float* bs = Bs[c & 1];
        #pragma unroll
        for (int k = 0; k < KC; k++) {
            float4 a0 = *(const float4*)(as + k * 132 + tr * 8);
            float4 a1 = *(const float4*)(as + k * 132 + tr * 8 + 4);
            float4 b0 = *(const float4*)(bs + k * 128 + tc * 8);
            float4 b1 = *(const float4*)(bs + k * 128 + tc * 8 + 4);
            ull ap[4] = { pk2(a0.x, a0.y), pk2(a0.z, a0.w),
                          pk2(a1.x, a1.y), pk2(a1.z, a1.w) };
            ull bd[8] = { pk2(b0.x, b0.x), pk2(b0.y, b0.y),
                          pk2(b0.z, b0.z), pk2(b0.w, b0.w),
                          pk2(b1.x, b1.x), pk2(b1.y, b1.y),
                          pk2(b1.z, b1.z), pk2(b1.w, b1.w) };
            #pragma unroll
            for (int i = 0; i < 4; i++)
                #pragma unroll
                for (int j = 0; j < 8; j++)
                    fma2(acc[i][j], ap[i], bd[j]);
        }
    }

    float bv[8];
    #pragma unroll
    for (int j = 0; j < 8; j++) bv[j] = bias[tc * 8 + j];
    #pragma unroll
    for (int i2 = 0; i2 < 4; i2++) {
        float2 v[8];
        #pragma unroll
        for (int j = 0; j < 8; j++) v[j] = upk2(acc[i2][j]);
        int r0 = row0 + tr * 8 + i2 * 2;
        if (r0 < nrows) {
            float4 o0 = make_float4(v[0].x + bv[0], v[1].x + bv[1],
                                    v[2].x + bv[2], v[3].x + bv[3]);
            float4 o1 = make_float4(v[4].x + bv[4], v[5].x + bv[5],
                                    v[6].x + bv[6], v[7].x + bv[7]);
            *(float4*)(g_hw + (size_t)r0 * HID + tc * 8)     = o0;
            *(float4*)(g_hw + (size_t)r0 * HID + tc * 8 + 4) = o1;
        }
        if (r0 + 1 < nrows) {
            float4 o0 = make_float4(v[0].y + bv[0], v[1].y + bv[1],
                                    v[2].y + bv[2], v[3].y + bv[3]);
            float4 o1 = make_float4(v[4].y + bv[4], v[5].y + bv[5],
                                    v[6].y + bv[6], v[7].y + bv[7]);
            *(float4*)(g_hw + (size_t)(r0 + 1) * HID + tc * 8)     = o0;
            *(float4*)(g_hw + (size_t)(r0 + 1) * HID + tc * 8 + 4) = o1;
        }
    }
}

// ---------------- aggregation (warp per node, gather unrolled x4) + BN stats ----------------
__global__ __launch_bounds__(256) void agg_kernel(int layer) {
    __shared__ float bsum[HID];
    __shared__ float bss[HID];
    int tid = threadIdx.x;
    for (int i = tid; i < HID; i += blockDim.x) { bsum[i] = 0.f; bss[i] = 0.f; }
    __syncthreads();

    int lane = tid & 31;
    int wglobal = (blockIdx.x * blockDim.x + tid) >> 5;
    int nwarps  = (gridDim.x * blockDim.x) >> 5;

    float ls0 = 0.f, ls1 = 0.f, ls2 = 0.f, ls3 = 0.f;
    float lq0 = 0.f, lq1 = 0.f, lq2 = 0.f, lq3 = 0.f;

    for (int n = wglobal; n < NODES; n += nwarps) {
        float dv = g_dinv[n];
        float sn = dv * dv;
        float4 a = ((const float4*)(g_hw + (size_t)n * HID))[lane];
        float4 acc = make_float4(a.x * sn, a.y * sn, a.z * sn, a.w * sn);
        int beg = g_off[n], end = g_off[n + 1];
        int i = beg;
        for (; i + 4 <= end; i += 4) {
            int2 e0 = g_csr[i],     e1 = g_csr[i + 1];
            int2 e2 = g_csr[i + 2], e3 = g_csr[i + 3];
            float w0 = __int_as_float(e0.y), w1 = __int_as_float(e1.y);
            float w2 = __int_as_float(e2.y), w3 = __int_as_float(e3.y);
            float4 v0 = ((const float4*)(g_hw + (size_t)e0.x * HID))[lane];
            float4 v1 = ((const float4*)(g_hw + (size_t)e1.x * HID))[lane];
            float4 v2 = ((const float4*)(g_hw + (size_t)e2.x * HID))[lane];
            float4 v3 = ((const float4*)(g_hw + (size_t)e3.x * HID))[lane];
            acc.x += w0 * v0.x + w1 * v1.x + w2 * v2.x + w3 * v3.x;
            acc.y += w0 * v0.y + w1 * v1.y + w2 * v2.y + w3 * v3.y;
            acc.z += w0 * v0.z + w1 * v1.z + w2 * v2.z + w3 * v3.z;
            acc.w += w0 * v0.w + w1 * v1.w + w2 * v2.w + w3 * v3.w;
        }
        for (; i + 2 <= end; i += 2) {
            int2 e0 = g_csr[i], e1 = g_csr[i + 1];
            float w0 = __int_as_float(e0.y), w1 = __int_as_float(e1.y);
            float4 v0 = ((const float4*)(g_hw + (size_t)e0.x * HID))[lane];
            float4 v1 = ((const float4*)(g_hw + (size_t)e1.x * HID))[lane];
            acc.x += w0 * v0.x + w1 * v1.x;
            acc.y += w0 * v0.y + w1 * v1.y;
            acc.z += w0 * v0.z + w1 * v1.z;
            acc.w += w0 * v0.w + w1 * v1.w;
        }
        if (i < end) {
            int2 e0 = g_csr[i];
            float w = __int_as_float(e0.y);
            float4 v = ((const float4*)(g_hw + (size_t)e0.x * HID))[lane];
            acc.x += w * v.x; acc.y += w * v.y;
            acc.z += w * v.z; acc.w += w * v.w;
        }
        ((float4*)(g_agg + (size_t)n * HID))[lane] = acc;
        ls0 += acc.x; ls1 += acc.y; ls2 += acc.z; ls3 += acc.w;
        lq0 += acc.x * acc.x; lq1 += acc.y * acc.y;
        lq2 += acc.z * acc.z; lq3 += acc.w * acc.w;
    }
    int c = lane * 4;
    atomicAdd(&bsum[c + 0], ls0); atomicAdd(&bsum[c + 1], ls1);
    atomicAdd(&bsum[c + 2], ls2); atomicAdd(&bsum[c + 3], ls3);
    atomicAdd(&bss[c + 0], lq0);  atomicAdd(&bss[c + 1], lq1);
    atomicAdd(&bss[c + 2], lq2);  atomicAdd(&bss[c + 3], lq3);
    __syncthreads();
    for (int i = tid; i < HID; i += blockDim.x) {
        atomicAdd(&g_stats[layer * 256 + i],       bsum[i]);
        atomicAdd(&g_stats[layer * 256 + HID + i], bss[i]);
    }
}

// ---------------- prep split: g_we has NO dependencies -> overlapped early ----------------
__global__ void prep_we_kernel(const float* __restrict__ l1w) {
    int j = threadIdx.x;   // 128
    float we = 0.f;
    #pragma unroll 8
    for (int k = 2 * HID; k < 4 * HID; k++)
        we += l1w[(size_t)k * HID + j];
    g_we[j] = we;
}

__global__ void prep_base_kernel(const float* __restrict__ l1w,
                                 const float* __restrict__ l1b,
                                 const int* __restrict__ curr) {
    __shared__ float xs[HID];
    int j = threadIdx.x;   // 128
    int c = *curr;
    float m = g_stats[2 * 256 + j] * (1.0f / NODES);
    float v = g_stats[2 * 256 + HID + j] * (1.0f / NODES) - m * m;
    float sc = rsqrtf(v + BN_EPS);
    xs[j] = fmaxf((g_agg[(size_t)c * HID + j] - m) * sc, 0.f);
    __syncthreads();
    float acc = 0.f;
    #pragma unroll 8
    for (int k = 0; k < HID; k++)
        acc += xs[k] * l1w[(size_t)(HID + k) * HID + j];
    g_base[j] = l1b[j] + acc;
}

// ==================== pipelined scoring (unchanged from R8) ====================
__global__ __launch_bounds__(256, 2) void score_kernel(
    const float* __restrict__ W,    // lin1_w rows 0..127
    const float* __restrict__ l2w, const float* __restrict__ l2b,
    const float* __restrict__ ecn, const float* __restrict__ parts,
    float* __restrict__ h, float* __restrict__ out)
{
    __shared__ float As[2][KC * 132];
    __shared__ float Bs[2][KC * 128];
    __shared__ float smean[HID], sscale[HID];
    __shared__ float sarr[128];
    __shared__ float pp[NPART];
    int tid = threadIdx.x;
    int tr = tid >> 4, tc = tid & 15;
    int row0 = blockIdx.x * 128;

    if (tid < HID) {
        float m = g_stats[2 * 256 + tid] * (1.0f / NODES);
        float v = g_stats[2 * 256 + HID + tid] * (1.0f / NODES) - m * m;
        smean[tid]  = m;
        sscale[tid] = rsqrtf(v + BN_EPS);
    }

    int rA[2], k4A[2];
    bool okA[2];
    #pragma unroll
    for (int i = 0; i < 2; i++) {
        int slot = tid + i * 256;
        rA[i]  = slot >> 2;
        k4A[i] = slot & 3;
        okA[i] = (row0 + rA[i]) < NODES;
    }
    int kB[2], c4B[2];
    #pragma unroll
    for (int i = 0; i < 2; i++) {
        int slot = tid + i * 256;
        kB[i]  = slot >> 5;
        c4B[i] = slot & 31;
    }

    ull acc[4][8];
    #pragma unroll
    for (int i = 0; i < 4; i++)
        #pragma unroll
        for (int j = 0; j < 8; j++) acc[i][j] = 0ull;

    float4 pa[2];
    #pragma unroll
    for (int i = 0; i < 2; i++)
        pa[i] = okA[i]
              ? *(const float4*)(g_agg + (size_t)(row0 + rA[i]) * HID + k4A[i] * 4)
              : make_float4(0.f, 0.f, 0.f, 0.f);
    #pragma unroll
    for (int i = 0; i < 2; i++)
        cpasync16(&Bs[0][kB[i] * 128 + c4B[i] * 4],
                  W + (size_t)kB[i] * HID + c4B[i] * 4);
    cpasync_commit();
    __syncthreads();   // smean/sscale ready
    #pragma unroll
    for (int i = 0; i < 2; i++) {
        float v4[4] = { pa[i].x, pa[i].y, pa[i].z, pa[i].w };
        float o4[4];
        #pragma unroll
        for (int j = 0; j < 4; j++) {
            int col = k4A[i] * 4 + j;
            o4[j] = fmaxf((v4[j] - smean[col]) * sscale[col], 0.f);
            As[0][col * 132 + rA[i]] = o4[j];
        }
        if (okA[i])
            *(float4*)(h + (size_t)(row0 + rA[i]) * HID + k4A[i] * 4) =
                make_float4(o4[0], o4[1], o4[2], o4[3]);
    }
    #pragma unroll
    for (int i = 0; i < 2; i++)
        pa[i] = okA[i]
              ? *(const float4*)(g_agg + (size_t)(row0 + rA[i]) * HID + KC + k4A[i] * 4)
              : make_float4(0.f, 0.f, 0.f, 0.f);

    #pragma unroll 1
    for (int c = 0; c < NCHUNK; c++) {
        cpasync_wait_all();
        __syncthreads();
        int nb = (c + 1) & 1;
        if (c + 1 < NCHUNK) {
            #pragma unroll
            for (int i = 0; i < 2; i++)
                cpasync16(&Bs[nb][kB[i] * 128 + c4B[i] * 4],
                          W + (size_t)((c + 1) * KC + kB[i]) * HID + c4B[i] * 4);
            cpasync_commit();
            #pragma unroll
            for (int i = 0; i < 2; i++) {
                float v4[4] = { pa[i].x, pa[i].y, pa[i].z, pa[i].w };
                float o4[4];
                #pragma unroll
                for (int j = 0; j < 4; j++) {
                    int col = (c + 1) * KC + k4A[i] * 4 + j;
                    o4[j] = fmaxf((v4[j] - smean[col]) * sscale[col], 0.f);
                    As[nb][(k4A[i] * 4 + j) * 132 + rA[i]] = o4[j];
                }
                if (okA[i])
                    *(float4*)(h + (size_t)(row0 + rA[i]) * HID
                               + (c + 1) * KC + k4A[i] * 4) =
                        make_float4(o4[0], o4[1], o4[2], o4[3]);
            }
        }
        if (c + 2 < NCHUNK) {
            #pragma unroll
            for (int i = 0; i < 2; i++)
                pa[i] = okA[i]
                      ? *(const float4*)(g_agg + (size_t)(row0 + rA[i]) * HID
                                         + (c + 2) * KC + k4A[i] * 4)
                      : make_float4(0.f, 0.f, 0.f, 0.f);
        }
        const float* as = As[c & 1];
        const float* bs = Bs[c & 1];
        #pragma unroll
        for (int k = 0; k < KC; k++) {
            float4 a0 = *(const float4*)(as + k * 132 + tr * 8);
            float4 a1 = *(const float4*)(as + k * 132 + tr * 8 + 4);
            float4 b0 = *(const float4*)(bs + k * 128 + tc * 8);
            float4 b1 = *(const float4*)(bs + k * 128 + tc * 8 + 4);
            ull ap[4] = { pk2(a0.x, a0.y), pk2(a0.z, a0.w),
                          pk2(a1.x, a1.y), pk2(a1.z, a1.w) };
            ull bd[8] = { pk2(b0.x, b0.x), pk2(b0.y, b0.y),
                          pk2(b0.z, b0.z), pk2(b0.w, b0.w),
                          pk2(b1.x, b1.x), pk2(b1.y, b1.y),
                          pk2(b1.z, b1.z), pk2(b1.w, b1.w) };
            #pragma unroll
            for (int i = 0; i < 4; i++)
                #pragma unroll
                for (int j = 0; j < 8; j++)
                    fma2(acc[i][j], ap[i], bd[j]);
        }
    }

    float w2[8], bb[8], wev[8];
    #pragma unroll
    for (int j = 0; j < 8; j++) {
        w2[j]  = l2w[tc * 8 + j];
        bb[j]  = g_base[tc * 8 + j];
        wev[j] = g_we[tc * 8 + j];
    }
    float b2 = l2b[0];
    #pragma unroll
    for (int i2 = 0; i2 < 4; i2++) {
        float2 v[8];
        #pragma unroll
        for (int j = 0; j < 8; j++) v[j] = upk2(acc[i2][j]);
        #pragma unroll
        for (int half = 0; half < 2; half++) {
            int row = row0 + tr * 8 + i2 * 2 + half;
            float e = (row < NODES) ? ecn[row] : 0.f;
            float s = 0.f;
            #pragma unroll
            for (int j = 0; j < 8; j++) {
                float val = half ? v[j].y : v[j].x;
                float t = val + bb[j] + e * wev[j];
                s += fmaxf(t, 0.f) * w2[j];
            }
            s += __shfl_xor_sync(0xffffffffu, s, 8, 16);
            s += __shfl_xor_sync(0xffffffffu, s, 4, 16);
            s += __shfl_xor_sync(0xffffffffu, s, 2, 16);
            s += __shfl_xor_sync(0xffffffffu, s, 1, 16);
            if (tc == 0) sarr[tr * 8 + i2 * 2 + half] = (row < NODES) ? (s + b2) : 0.f;
        }
    }
    if (tid < NPART) pp[tid] = 0.f;
    __syncthreads();
    int p = tid & 31, g = tid >> 5;
    float psum = 0.f;
    for (int r = g * 16; r < g * 16 + 16; r++) {
        int row = row0 + r;
        if (row < NODES) psum += sarr[r] * parts[(size_t)row * NPART + p];
    }
    atomicAdd(&pp[p], psum);
    __syncthreads();
    if (tid < NPART) atomicAdd(&out[tid], pp[tid]);
}

// ---------------- launcher ----------------
extern "C" void kernel_launch(void* const* d_in, const int* in_sizes, int n_in,
                              void* d_out, int out_size) {
    const float* x      = (const float*)d_in[0];
    const int*   ei     = (const int*)d_in[1];
    const float* ew     = (const float*)d_in[2];
    const float* parts  = (const float*)d_in[3];
    // d_in[4] = node_weights (unused by reference)
    const float* ecn    = (const float*)d_in[5];
    const float* conv_w = (const float*)d_in[6];
    const float* conv_b = (const float*)d_in[7];
    const float* l1w    = (const float*)d_in[8];
    const float* l1b    = (const float*)d_in[9];
    const float* l2w    = (const float*)d_in[10];
    const float* l2b    = (const float*)d_in[11];
    const int*   curr   = (const int*)d_in[12];

    float* out = (float*)d_out;          // [0:32) partition scores
    float* h   = out + NPART;            // [32 : 32+N*H) final h

    // exact single-wave grid for agg (pure host queries; graph-legal)
    int agg_blocks = 1184;
    {
        int dev = 0, sms = 0, maxb = 0;
        if (cudaGetDevice(&dev) == cudaSuccess &&
            cudaDeviceGetAttribute(&sms, cudaDevAttrMultiProcessorCount, dev) == cudaSuccess &&
            cudaOccupancyMaxActiveBlocksPerMultiprocessor(&maxb, agg_kernel, 256, 0) == cudaSuccess &&
            sms > 0 && maxb > 0) {
            agg_blocks = sms * maxb;
        }
    }

    cudaStream_t sG;
    cudaStreamCreateWithFlags(&sG, cudaStreamNonBlocking);
    cudaEvent_t evFork, evJoin;
    cudaEventCreateWithFlags(&evFork, cudaEventDisableTiming);
    cudaEventCreateWithFlags(&evJoin, cudaEventDisableTiming);

    const int gemm_blocks = (NODES + 127) / 128;   // 391

    cudaEventRecord(evFork, 0);
    cudaStreamWaitEvent(sG, evFork, 0);

    // ---- setup chain on default stream ----
    zero_init_kernel<<<(NODES + 255) / 256, 256>>>(out);         // 1
    deg_count_kernel<<<(NE + 255) / 256, 256>>>(ei, ew);         // 2
    scan_kernel2<<<NSB, SBLK>>>();                               // 3 (merged scan + dinv)
    csr_fill_kernel<<<(NE + 255) / 256, 256>>>(ei, ew);          // 4 <- ncu target

    // ---- overlapped on sG: we-sums (no deps) + gemm0 (depends only on x) ----
    prep_we_kernel<<<1, 128, 0, sG>>>(l1w);                      // 5
    gemm_kernel<<<gemm_blocks, 256, 0, sG>>>(x, conv_w, conv_b, -1, NODES);  // 6

    cudaEventRecord(evJoin, sG);
    cudaStreamWaitEvent(0, evJoin, 0);

    agg_kernel<<<agg_blocks, 256>>>(0);
    gemm_kernel<<<gemm_blocks, 256>>>(nullptr, conv_w + 1 * HID * HID,
                                      conv_b + 1 * HID, 0, NODES);
    agg_kernel<<<agg_blocks, 256>>>(1);
    gemm_kernel<<<gemm_blocks, 256>>>(nullptr, conv_w + 2 * HID * HID,
                                      conv_b + 2 * HID, 1, NODES);
    agg_kernel<<<agg_blocks, 256>>>(2);

    prep_base_kernel<<<1, 128>>>(l1w, l1b, curr);
    score_kernel<<<gemm_blocks, 256>>>(l1w, l2w, l2b, ecn, parts, h, out);
}